// round 1
// baseline (speedup 1.0000x reference)
#include <cuda_runtime.h>
#include <cstdint>
#include <cstddef>

#define B_   32
#define C_   256
#define H_   56
#define W_   56
#define HW_  3136
#define G_   8
#define CG_  32
#define OC_  256

// ---------------- scratch (device globals; no allocation allowed) ----------------
__device__ float d_mu[B_ * G_];
__device__ float d_rs[B_ * G_];
__device__ float d_scale[OC_];                 // alpha_oc * a_c / 255
__device__ uint4 d_hq4[(size_t)B_ * HW_ * 16]; // NHWC uint8 activations (256B/pixel)
__device__ uint4 d_wt4[OC_ * 144];             // int8 weights [oc][k=9][ic=256]

// dp4a: a = packed u8 (activations), b = packed s8 (ternary weights)
__device__ __forceinline__ int dp4a_us(unsigned a, unsigned b, int c) {
    int d;
    asm("dp4a.u32.s32 %0, %1, %2, %3;" : "=r"(d) : "r"(a), "r"(b), "r"(c));
    return d;
}

// ---------------- kernel 1: GroupNorm statistics ----------------
__global__ void gn_stats_kernel(const float* __restrict__ x) {
    int bg = blockIdx.x;              // b*8 + g
    int b = bg >> 3, g = bg & 7;
    const float* xp = x + ((size_t)b * C_ + (size_t)g * CG_) * HW_;
    const int N = CG_ * HW_;          // 100352
    int tid = threadIdx.x;
    float s = 0.f, s2 = 0.f;
    for (int i = tid; i < N; i += 256) {
        float v = xp[i];
        s += v;
        s2 += v * v;
    }
    __shared__ float r1[256], r2[256];
    r1[tid] = s; r2[tid] = s2;
    __syncthreads();
    for (int o = 128; o; o >>= 1) {
        if (tid < o) { r1[tid] += r1[tid + o]; r2[tid] += r2[tid + o]; }
        __syncthreads();
    }
    if (tid == 0) {
        float mu = r1[0] / (float)N;
        float var = r2[0] / (float)N - mu * mu;
        d_mu[bg] = mu;
        d_rs[bg] = rsqrtf(var + 1e-5f);
    }
}

// ---------------- kernel 2: normalize + ReLU^2 + PACT quant + NCHW->NHWC ----------------
// grid (98, 8, 32), block (32, 8). Tile: 32 channels x 32 pixels.
__global__ void quant_kernel(const float* __restrict__ x,
                             const float* __restrict__ gamma,
                             const float* __restrict__ beta,
                             const float* __restrict__ a_ptr) {
    __shared__ unsigned char tile[32][33];
    int b = blockIdx.z;
    int c0 = blockIdx.y * 32;   // group index == blockIdx.y (CG_=32)
    int p0 = blockIdx.x * 32;
    int tx = threadIdx.x, ty = threadIdx.y;

    float a_c = fmaxf(a_ptr[0], 0.f) + 1e-8f;
    float S = 255.f / a_c;
    float mu = d_mu[b * 8 + blockIdx.y];
    float rs = d_rs[b * 8 + blockIdx.y];

#pragma unroll
    for (int i = 0; i < 4; i++) {
        int cl = ty + i * 8;
        int c = c0 + cl;
        float v = x[((size_t)b * C_ + c) * HW_ + p0 + tx];
        float xn = (v - mu) * rs * gamma[c] + beta[c];
        float r = fmaxf(xn, 0.f);
        float h = r * r;
        float yv = fminf(h, a_c);
        tile[cl][tx] = (unsigned char)(int)rintf(yv * S);  // rintf = round-half-even
    }
    __syncthreads();
    unsigned char* hq = (unsigned char*)d_hq4;
#pragma unroll
    for (int i = 0; i < 4; i++) {
        int p = p0 + ty + i * 8;
        hq[((size_t)b * HW_ + p) * 256 + c0 + tx] = tile[tx][ty + i * 8];
    }
}

// ---------------- kernel 3: ternarize weights ----------------
// one block per oc, 256 threads. weight_fp layout OIHW: [oc][ic][3][3] (2304 per oc).
__global__ void tern_kernel(const float* __restrict__ w,
                            const float* __restrict__ a_ptr) {
    int oc = blockIdx.x, tid = threadIdx.x;
    const float* wp = w + (size_t)oc * 2304;
    __shared__ float red[256], red2[256];
    __shared__ float t_sh;

    float s = 0.f;
    for (int i = tid; i < 2304; i += 256) s += fabsf(wp[i]);
    red[tid] = s;
    __syncthreads();
    for (int o = 128; o; o >>= 1) {
        if (tid < o) red[tid] += red[tid + o];
        __syncthreads();
    }
    if (tid == 0) t_sh = 0.05f * red[0] / 2304.0f;
    __syncthreads();
    float t = t_sh;

    float sa = 0.f, sm = 0.f;
    for (int i = tid; i < 2304; i += 256) {
        float aw = fabsf(wp[i]);
        if (aw > t) { sa += aw; sm += 1.f; }
    }
    red[tid] = sa; red2[tid] = sm;
    __syncthreads();
    for (int o = 128; o; o >>= 1) {
        if (tid < o) { red[tid] += red[tid + o]; red2[tid] += red2[tid + o]; }
        __syncthreads();
    }
    if (tid == 0) {
        float alpha = red[0] / (red2[0] + 1e-8f);
        float a_c = fmaxf(a_ptr[0], 0.f) + 1e-8f;
        d_scale[oc] = alpha * a_c / 255.0f;
    }
    signed char* wt = (signed char*)d_wt4;
    for (int i = tid; i < 2304; i += 256) {
        float wv = wp[i];
        float aw = fabsf(wv);
        signed char q = (aw > t) ? (wv > 0.f ? (signed char)1 : (signed char)-1)
                                 : (signed char)0;
        int ic = i / 9, k = i - ic * 9;        // [ic][ky][kx] -> [k][ic]
        wt[(size_t)oc * 2304 + k * 256 + ic] = q;
    }
}

// ---------------- kernel 4: int8 dp4a conv 3x3 pad 1 ----------------
// grid (16, 56, 32): (oc-block of 16, output row y, batch). block (14,16) = 224 thr.
// smem: input 3 rows x 58 padded pixels x 16 uint4 (XOR-swizzled) + 16 oc weights.
#define SIN_ROW 928            // 58 * 16 uint4 per row
#define SIN_TOT 2784           // 3 * 928
#define SW_STRIDE 145          // 144 + 1 pad (kills bank-group aliasing)
#define SMEM_U4 (SIN_TOT + 16 * SW_STRIDE)   // 5104 uint4 = 81664 B

__global__ void __launch_bounds__(224, 2)
conv_kernel(const float* __restrict__ bias, float* __restrict__ out) {
    extern __shared__ uint4 smem[];
    uint4* sIn = smem;            // [3][58][16] swizzled
    uint4* sW  = smem + SIN_TOT;  // [16][145]

    int tx = threadIdx.x, ty = threadIdx.y;
    int tid = ty * 14 + tx;
    int oc0 = blockIdx.x * 16;
    int y = blockIdx.y;
    int b = blockIdx.z;

    // weights: 16 oc x 144 uint4
    for (int idx = tid; idx < 2304; idx += 224) {
        int ocl = idx / 144, rem = idx - ocl * 144;
        sW[ocl * SW_STRIDE + rem] = d_wt4[(size_t)(oc0 + ocl) * 144 + rem];
    }
    // input: rows y-1..y+1, padded pixels -1..56, swizzled chunk = c4 ^ (px&15)
    const uint4 zz = make_uint4(0u, 0u, 0u, 0u);
    for (int idx = tid; idx < SIN_TOT; idx += 224) {
        int r = idx / SIN_ROW, rem = idx - r * SIN_ROW;
        int px = rem >> 4, c4 = rem & 15;
        int yy = y - 1 + r, xx = px - 1;
        uint4 v = zz;
        if (yy >= 0 && yy < 56 && xx >= 0 && xx < 56)
            v = d_hq4[(((size_t)b * HW_) + yy * 56 + xx) * 16 + c4];
        sIn[r * SIN_ROW + px * 16 + (c4 ^ (px & 15))] = v;
    }
    __syncthreads();

    int acc0 = 0, acc1 = 0, acc2 = 0, acc3 = 0;
#pragma unroll 1
    for (int ky = 0; ky < 3; ky++) {
        int base = ky * SIN_ROW;
#pragma unroll
        for (int kx = 0; kx < 3; kx++) {
            int x0 = tx + kx, x1 = x0 + 14, x2 = x0 + 28, x3 = x0 + 42; // padded px
            int p0 = base + x0 * 16, m0 = x0 & 15;
            int p1 = base + x1 * 16, m1 = x1 & 15;
            int p2 = base + x2 * 16, m2 = x2 & 15;
            int p3 = base + x3 * 16, m3 = x3 & 15;
            const uint4* wp = sW + ty * SW_STRIDE + (ky * 3 + kx) * 16;
#pragma unroll
            for (int w4 = 0; w4 < 16; w4++) {
                uint4 wv = wp[w4];
                uint4 i0 = sIn[p0 + (w4 ^ m0)];
                uint4 i1 = sIn[p1 + (w4 ^ m1)];
                uint4 i2 = sIn[p2 + (w4 ^ m2)];
                uint4 i3 = sIn[p3 + (w4 ^ m3)];
                acc0 = dp4a_us(i0.x, wv.x, acc0);
                acc0 = dp4a_us(i0.y, wv.y, acc0);
                acc0 = dp4a_us(i0.z, wv.z, acc0);
                acc0 = dp4a_us(i0.w, wv.w, acc0);
                acc1 = dp4a_us(i1.x, wv.x, acc1);
                acc1 = dp4a_us(i1.y, wv.y, acc1);
                acc1 = dp4a_us(i1.z, wv.z, acc1);
                acc1 = dp4a_us(i1.w, wv.w, acc1);
                acc2 = dp4a_us(i2.x, wv.x, acc2);
                acc2 = dp4a_us(i2.y, wv.y, acc2);
                acc2 = dp4a_us(i2.z, wv.z, acc2);
                acc2 = dp4a_us(i2.w, wv.w, acc2);
                acc3 = dp4a_us(i3.x, wv.x, acc3);
                acc3 = dp4a_us(i3.y, wv.y, acc3);
                acc3 = dp4a_us(i3.z, wv.z, acc3);
                acc3 = dp4a_us(i3.w, wv.w, acc3);
            }
        }
    }

    int oc = oc0 + ty;
    float sc = d_scale[oc];
    float bv = bias[oc];
    size_t ob = ((size_t)b * OC_ + oc) * HW_ + (size_t)y * 56 + tx;
    out[ob]      = fmaf(sc, (float)acc0, bv);
    out[ob + 14] = fmaf(sc, (float)acc1, bv);
    out[ob + 28] = fmaf(sc, (float)acc2, bv);
    out[ob + 42] = fmaf(sc, (float)acc3, bv);
}

// ---------------- launch ----------------
extern "C" void kernel_launch(void* const* d_in, const int* in_sizes, int n_in,
                              void* d_out, int out_size) {
    const float* x     = (const float*)d_in[0];
    const float* gamma = (const float*)d_in[1];
    const float* beta  = (const float*)d_in[2];
    const float* a     = (const float*)d_in[3];
    const float* wfp   = (const float*)d_in[4];
    const float* bias  = (const float*)d_in[5];
    float* out = (float*)d_out;

    (void)in_sizes; (void)n_in; (void)out_size;

    gn_stats_kernel<<<B_ * G_, 256>>>(x);
    quant_kernel<<<dim3(HW_ / 32, C_ / 32, B_), dim3(32, 8)>>>(x, gamma, beta, a);
    tern_kernel<<<OC_, 256>>>(wfp, a);

    const int smem_bytes = SMEM_U4 * (int)sizeof(uint4);  // 81664
    cudaFuncSetAttribute(conv_kernel, cudaFuncAttributeMaxDynamicSharedMemorySize,
                         smem_bytes);
    conv_kernel<<<dim3(OC_ / 16, H_, B_), dim3(14, 16), smem_bytes>>>(bias, out);
}

// round 5
// speedup vs baseline: 1.3803x; 1.3803x over previous
#include <cuda_runtime.h>
#include <cstdint>
#include <cstddef>

#define B_   32
#define C_   256
#define H_   56
#define W_   56
#define HW_  3136
#define OC_  256
#define QROWS 3600                         // 60x60 padded pixel space per batch

// ---------------- scratch (device globals) ----------------
__device__ float d_mu[B_ * 8];
__device__ float d_rs[B_ * 8];
__device__ float d_scale[OC_];             // alpha_oc * a_c / 255
__device__ unsigned char d_hq[((size_t)B_ * QROWS + 128) * 256];  // padded NHWC u8 (+tail pad)
__device__ signed char  d_ws[9 * 256 * 256];                      // [tap][oc][ic] in {-1,0,1}

// ======================= PTX helpers =======================
__device__ __forceinline__ uint32_t smem_u32(const void* p) {
    uint32_t a;
    asm("{ .reg .u64 t; cvta.to.shared.u64 t, %1; cvt.u32.u64 %0, t; }" : "=r"(a) : "l"(p));
    return a;
}
#define CP16(dst, src) \
    asm volatile("cp.async.cg.shared.global [%0], [%1], 16;" :: "r"(dst), "l"(src) : "memory")
#define CP_COMMIT() asm volatile("cp.async.commit_group;" ::: "memory")
#define CP_WAIT2()  asm volatile("cp.async.wait_group 2;" ::: "memory")

__device__ __forceinline__ void ldsm4(uint32_t* r, uint32_t addr) {
    asm volatile("ldmatrix.sync.aligned.m8n8.x4.shared.b16 {%0,%1,%2,%3}, [%4];"
                 : "=r"(r[0]), "=r"(r[1]), "=r"(r[2]), "=r"(r[3]) : "r"(addr));
}
__device__ __forceinline__ void ldsm2(uint32_t* r, uint32_t addr) {
    asm volatile("ldmatrix.sync.aligned.m8n8.x2.shared.b16 {%0,%1}, [%2];"
                 : "=r"(r[0]), "=r"(r[1]) : "r"(addr));
}
__device__ __forceinline__ void mma_u8s8(int* c, const uint32_t* a, const uint32_t* b) {
    asm volatile(
        "mma.sync.aligned.m16n8k32.row.col.s32.u8.s8.s32 "
        "{%0,%1,%2,%3}, {%4,%5,%6,%7}, {%8,%9}, {%0,%1,%2,%3};"
        : "+r"(c[0]), "+r"(c[1]), "+r"(c[2]), "+r"(c[3])
        : "r"(a[0]), "r"(a[1]), "r"(a[2]), "r"(a[3]), "r"(b[0]), "r"(b[1]));
}

// ---------------- kernel 1: GroupNorm statistics ----------------
__global__ void gn_stats_kernel(const float* __restrict__ x) {
    int bg = blockIdx.x;
    int b = bg >> 3, g = bg & 7;
    const float4* xp = (const float4*)(x + ((size_t)b * C_ + (size_t)g * 32) * HW_);
    const int N4 = 32 * HW_ / 4;
    int tid = threadIdx.x;
    float s = 0.f, s2 = 0.f;
    for (int i = tid; i < N4; i += 256) {
        float4 v = xp[i];
        s += v.x + v.y + v.z + v.w;
        s2 += v.x * v.x + v.y * v.y + v.z * v.z + v.w * v.w;
    }
    __shared__ float r1[256], r2[256];
    r1[tid] = s; r2[tid] = s2;
    __syncthreads();
    for (int o = 128; o; o >>= 1) {
        if (tid < o) { r1[tid] += r1[tid + o]; r2[tid] += r2[tid + o]; }
        __syncthreads();
    }
    if (tid == 0) {
        const float N = (float)(32 * HW_);
        float mu = r1[0] / N;
        float var = r2[0] / N - mu * mu;
        d_mu[bg] = mu;
        d_rs[bg] = rsqrtf(var + 1e-5f);
    }
}

// ---------------- kernel 1b: zero padding rows of d_hq ----------------
__global__ void pad_zero_kernel() {
    int p = blockIdx.x, b = blockIdx.y;
    if (b == B_) {                              // tail overread pad rows
        if (p < 128)
            ((uint32_t*)(d_hq + ((size_t)B_ * QROWS + p) * 256))[threadIdx.x] = 0u;
        return;
    }
    int y = p / 60, x = p - y * 60;
    if (y == 0 || y >= 57 || x == 0 || x >= 57)
        ((uint32_t*)(d_hq + ((size_t)b * QROWS + p) * 256))[threadIdx.x] = 0u;
}

// ---------------- kernel 2: GN + ReLU^2 + PACT quant -> padded NHWC u8 ----------------
__global__ void quant_kernel(const float* __restrict__ x,
                             const float* __restrict__ gamma,
                             const float* __restrict__ beta,
                             const float* __restrict__ a_ptr) {
    __shared__ unsigned char tile[32][33];
    int b = blockIdx.z;
    int c0 = blockIdx.y * 32;
    int p0 = blockIdx.x * 32;
    int tx = threadIdx.x, ty = threadIdx.y;

    float a_c = fmaxf(a_ptr[0], 0.f) + 1e-8f;
    float S = 255.f / a_c;
    float mu = d_mu[b * 8 + blockIdx.y];
    float rs = d_rs[b * 8 + blockIdx.y];

#pragma unroll
    for (int i = 0; i < 4; i++) {
        int cl = ty + i * 8;
        int c = c0 + cl;
        float v = x[((size_t)b * C_ + c) * HW_ + p0 + tx];
        float xn = (v - mu) * rs * gamma[c] + beta[c];
        float r = fmaxf(xn, 0.f);
        float h = r * r;
        float yv = fminf(h, a_c);
        tile[cl][tx] = (unsigned char)(int)rintf(yv * S);
    }
    __syncthreads();
#pragma unroll
    for (int i = 0; i < 4; i++) {
        int p = p0 + ty + i * 8;           // valid pixel 0..3135
        int y = p / 56, xx = p - y * 56;
        size_t q = (size_t)(y + 1) * 60 + (xx + 1);
        d_hq[((size_t)b * QROWS + q) * 256 + c0 + tx] = tile[tx][ty + i * 8];
    }
}

// ---------------- kernel 3: ternarize weights -> s8 [tap][oc][ic] ----------------
__global__ void tern_kernel(const float* __restrict__ w,
                            const float* __restrict__ a_ptr) {
    int oc = blockIdx.x, tid = threadIdx.x;
    const float* wp = w + (size_t)oc * 2304;
    __shared__ float red[256], red2[256];
    __shared__ float t_sh;

    float s = 0.f;
    for (int i = tid; i < 2304; i += 256) s += fabsf(wp[i]);
    red[tid] = s;
    __syncthreads();
    for (int o = 128; o; o >>= 1) {
        if (tid < o) red[tid] += red[tid + o];
        __syncthreads();
    }
    if (tid == 0) t_sh = 0.05f * red[0] / 2304.0f;
    __syncthreads();
    float t = t_sh;

    float sa = 0.f, sm = 0.f;
    for (int i = tid; i < 2304; i += 256) {
        float aw = fabsf(wp[i]);
        if (aw > t) { sa += aw; sm += 1.f; }
    }
    red[tid] = sa; red2[tid] = sm;
    __syncthreads();
    for (int o = 128; o; o >>= 1) {
        if (tid < o) { red[tid] += red[tid + o]; red2[tid] += red2[tid + o]; }
        __syncthreads();
    }
    if (tid == 0) {
        float alpha = red[0] / (red2[0] + 1e-8f);
        float a_c = fmaxf(a_ptr[0], 0.f) + 1e-8f;
        d_scale[oc] = alpha * a_c / 255.0f;
    }
    for (int i = tid; i < 2304; i += 256) {
        float wv = wp[i];
        signed char q = (fabsf(wv) > t) ? (wv > 0.f ? (signed char)1 : (signed char)-1)
                                        : (signed char)0;
        int ic = i / 9, k = i - ic * 9;    // tap = ky*3+kx
        d_ws[((size_t)k * 256 + oc) * 256 + ic] = q;
    }
}

// ---------------- kernel 4: IMMA implicit-GEMM conv ----------------
// grid (28, 2, 32): M=128 output pixels (q = oy*60+ox), N=128 oc, K=2304 = 36 chunks of 64.
// smem: 4 stages x (A 128x80 + B 128x80) = 81920 B; epilogue reuses as int[128][132].
#define NST 4
#define STAGE_B 20480
#define SMEM_CONV 81920

__global__ void __launch_bounds__(256, 1)
conv_mma_kernel(const float* __restrict__ bias, float* __restrict__ out) {
    extern __shared__ char smem[];
    uint32_t sbase = smem_u32(smem);
    int tid = threadIdx.x;
    int wid = tid >> 5, lane = tid & 31;
    int warp_m = wid >> 2, warp_n = wid & 3;
    int b = blockIdx.z;
    int n0 = blockIdx.y * 128;
    int q0 = blockIdx.x * 128;
    size_t bq0 = (size_t)b * QROWS + q0;

    // cp.async role: threads 0..127 load A row=tid, 128..255 load B row=tid-128
    bool isA = tid < 128;
    int lrow = isA ? tid : tid - 128;
    uint32_t sdst0 = sbase + (isA ? 0u : 10240u) + (uint32_t)lrow * 80u;

    // ldmatrix per-lane offsets
    int grp = lane >> 3, r8 = lane & 7;
    uint32_t aoff[4], boff[4];
#pragma unroll
    for (int t = 0; t < 4; t++)
        aoff[t] = sbase +
            (uint32_t)((warp_m * 64 + t * 16 + (grp & 1) * 8 + r8) * 80 + (grp >> 1) * 16);
    int bl = lane & 15;
#pragma unroll
    for (int u = 0; u < 4; u++)
        boff[u] = sbase + 10240u +
            (uint32_t)((warp_n * 32 + u * 8 + (bl & 7)) * 80 + (bl >> 3) * 16);

    int acc[4][4][4];
#pragma unroll
    for (int t = 0; t < 4; t++)
#pragma unroll
        for (int u = 0; u < 4; u++)
#pragma unroll
            for (int k = 0; k < 4; k++) acc[t][u][k] = 0;

    // stage issue: output pixel q reads padded input pixel q + ky*60 + kx
    auto issue = [&](int s) {
        int st = s & (NST - 1);
        int tap = s >> 2, cc = s & 3;
        int ky = tap / 3, kx = tap - ky * 3;
        const char* g;
        if (isA)
            g = (const char*)(d_hq + (bq0 + (size_t)(ky * 60 + kx + lrow)) * 256 + cc * 64);
        else
            g = (const char*)(d_ws + ((size_t)(tap * 256 + n0 + lrow)) * 256 + cc * 64);
        uint32_t d = sdst0 + (uint32_t)st * STAGE_B;
        CP16(d, g); CP16(d + 16, g + 16); CP16(d + 32, g + 32); CP16(d + 48, g + 48);
        CP_COMMIT();
    };

    issue(0); issue(1); issue(2);

#pragma unroll 1
    for (int s = 0; s < 36; s++) {
        int st = s & (NST - 1);
        CP_WAIT2();
        __syncthreads();
        uint32_t so = (uint32_t)st * STAGE_B;
#pragma unroll
        for (int ks = 0; ks < 2; ks++) {
            uint32_t kb = so + ks * 32;
            uint32_t afr[4][4], bfr[4][2];
#pragma unroll
            for (int t = 0; t < 4; t++) ldsm4(afr[t], aoff[t] + kb);
#pragma unroll
            for (int u = 0; u < 4; u++) ldsm2(bfr[u], boff[u] + kb);
#pragma unroll
            for (int t = 0; t < 4; t++)
#pragma unroll
                for (int u = 0; u < 4; u++)
                    mma_u8s8(acc[t][u], afr[t], bfr[u]);
        }
        if (s + 3 < 36) issue(s + 3);
        else CP_COMMIT();                 // empty group keeps wait_group accounting aligned
    }

    // ---------------- epilogue: stage via smem, coalesced NCHW stores ----------------
    // q = q0 + m is the OUTPUT pixel at valid coords (y = q/60, x = q%60),
    // valid iff y < 56 && x < 56 (matches A offset convention q + ky*60 + kx).
    __syncthreads();
    int* sep = (int*)smem;                // [128 oc][pitch 132]
#pragma unroll
    for (int t = 0; t < 4; t++) {
        int m = warp_m * 64 + t * 16 + (lane >> 2);
#pragma unroll
        for (int u = 0; u < 4; u++) {
            int n = warp_n * 32 + u * 8 + 2 * (lane & 3);
            sep[n * 132 + m]           = acc[t][u][0];
            sep[(n + 1) * 132 + m]     = acc[t][u][1];
            sep[n * 132 + m + 8]       = acc[t][u][2];
            sep[(n + 1) * 132 + m + 8] = acc[t][u][3];
        }
    }
    __syncthreads();

#pragma unroll 1
    for (int i = 0; i < 16; i++) {
        int ol = wid + i * 8;
        int oc = n0 + ol;
        float sc = d_scale[oc];
        float bv = __ldg(&bias[oc]);
        float* orow = out + ((size_t)(b * OC_ + oc)) * HW_;
#pragma unroll
        for (int qc = 0; qc < 4; qc++) {
            int m = qc * 32 + lane;
            int q = q0 + m;
            int y = q / 60, x = q - y * 60;
            if (y < 56 && x < 56)
                orow[y * 56 + x] = fmaf(sc, (float)sep[ol * 132 + m], bv);
        }
    }
}

// ---------------- launch ----------------
extern "C" void kernel_launch(void* const* d_in, const int* in_sizes, int n_in,
                              void* d_out, int out_size) {
    const float* x     = (const float*)d_in[0];
    const float* gamma = (const float*)d_in[1];
    const float* beta  = (const float*)d_in[2];
    const float* a     = (const float*)d_in[3];
    const float* wfp   = (const float*)d_in[4];
    const float* bias  = (const float*)d_in[5];
    float* out = (float*)d_out;
    (void)in_sizes; (void)n_in; (void)out_size;

    gn_stats_kernel<<<B_ * 8, 256>>>(x);
    pad_zero_kernel<<<dim3(QROWS, B_ + 1), 64>>>();
    quant_kernel<<<dim3(HW_ / 32, C_ / 32, B_), dim3(32, 8)>>>(x, gamma, beta, a);
    tern_kernel<<<OC_, 256>>>(wfp, a);

    cudaFuncSetAttribute(conv_mma_kernel,
                         cudaFuncAttributeMaxDynamicSharedMemorySize, SMEM_CONV);
    conv_mma_kernel<<<dim3(28, 2, B_), 256, SMEM_CONV>>>(bias, out);
}

// round 6
// speedup vs baseline: 2.1054x; 1.5253x over previous
#include <cuda_runtime.h>
#include <cstdint>
#include <cstddef>

#define B_   32
#define C_   256
#define H_   56
#define W_   56
#define HW_  3136
#define OC_  256
#define QROWS 3600                         // 60x60 padded pixel space per batch

// ---------------- scratch (device globals) ----------------
__device__ float d_mu[B_ * 8];
__device__ float d_rs[B_ * 8];
__device__ float d_scale[OC_];             // alpha_oc * a_c / 255
__device__ unsigned char d_hq[((size_t)B_ * QROWS + 128) * 256];  // padded NHWC u8 (+tail pad)
__device__ signed char  d_ws[9 * 256 * 256];                      // [tap][oc][ic] in {-1,0,1}

// ======================= PTX helpers =======================
__device__ __forceinline__ uint32_t smem_u32(const void* p) {
    uint32_t a;
    asm("{ .reg .u64 t; cvta.to.shared.u64 t, %1; cvt.u32.u64 %0, t; }" : "=r"(a) : "l"(p));
    return a;
}
#define CP16(dst, src) \
    asm volatile("cp.async.cg.shared.global [%0], [%1], 16;" :: "r"(dst), "l"(src) : "memory")
#define CP_COMMIT() asm volatile("cp.async.commit_group;" ::: "memory")
#define CP_WAIT2()  asm volatile("cp.async.wait_group 2;" ::: "memory")

__device__ __forceinline__ void ldsm4(uint32_t* r, uint32_t addr) {
    asm volatile("ldmatrix.sync.aligned.m8n8.x4.shared.b16 {%0,%1,%2,%3}, [%4];"
                 : "=r"(r[0]), "=r"(r[1]), "=r"(r[2]), "=r"(r[3]) : "r"(addr));
}
__device__ __forceinline__ void ldsm2(uint32_t* r, uint32_t addr) {
    asm volatile("ldmatrix.sync.aligned.m8n8.x2.shared.b16 {%0,%1}, [%2];"
                 : "=r"(r[0]), "=r"(r[1]) : "r"(addr));
}
__device__ __forceinline__ void mma_u8s8(int* c, const uint32_t* a, const uint32_t* b) {
    asm volatile(
        "mma.sync.aligned.m16n8k32.row.col.s32.u8.s8.s32 "
        "{%0,%1,%2,%3}, {%4,%5,%6,%7}, {%8,%9}, {%0,%1,%2,%3};"
        : "+r"(c[0]), "+r"(c[1]), "+r"(c[2]), "+r"(c[3])
        : "r"(a[0]), "r"(a[1]), "r"(a[2]), "r"(a[3]), "r"(b[0]), "r"(b[1]));
}

// ---------------- kernel 1: GroupNorm statistics ----------------
__global__ void gn_stats_kernel(const float* __restrict__ x) {
    int bg = blockIdx.x;
    int b = bg >> 3, g = bg & 7;
    const float4* xp = (const float4*)(x + ((size_t)b * C_ + (size_t)g * 32) * HW_);
    const int N4 = 32 * HW_ / 4;
    int tid = threadIdx.x;
    float s = 0.f, s2 = 0.f;
    for (int i = tid; i < N4; i += 256) {
        float4 v = xp[i];
        s += v.x + v.y + v.z + v.w;
        s2 += v.x * v.x + v.y * v.y + v.z * v.z + v.w * v.w;
    }
    __shared__ float r1[256], r2[256];
    r1[tid] = s; r2[tid] = s2;
    __syncthreads();
    for (int o = 128; o; o >>= 1) {
        if (tid < o) { r1[tid] += r1[tid + o]; r2[tid] += r2[tid + o]; }
        __syncthreads();
    }
    if (tid == 0) {
        const float N = (float)(32 * HW_);
        float mu = r1[0] / N;
        float var = r2[0] / N - mu * mu;
        d_mu[bg] = mu;
        d_rs[bg] = rsqrtf(var + 1e-5f);
    }
}

// ---------------- kernel 1b: zero padding rows of d_hq ----------------
__global__ void pad_zero_kernel() {
    int p = blockIdx.x, b = blockIdx.y;
    if (b == B_) {                              // tail overread pad rows
        if (p < 128)
            ((uint32_t*)(d_hq + ((size_t)B_ * QROWS + p) * 256))[threadIdx.x] = 0u;
        return;
    }
    int y = p / 60, x = p - y * 60;
    if (y == 0 || y >= 57 || x == 0 || x >= 57)
        ((uint32_t*)(d_hq + ((size_t)b * QROWS + p) * 256))[threadIdx.x] = 0u;
}

// ---------------- kernel 2: GN + ReLU^2 + PACT quant -> padded NHWC u8 ----------------
__global__ void quant_kernel(const float* __restrict__ x,
                             const float* __restrict__ gamma,
                             const float* __restrict__ beta,
                             const float* __restrict__ a_ptr) {
    __shared__ unsigned char tile[32][33];
    int b = blockIdx.z;
    int c0 = blockIdx.y * 32;
    int p0 = blockIdx.x * 32;
    int tx = threadIdx.x, ty = threadIdx.y;

    float a_c = fmaxf(a_ptr[0], 0.f) + 1e-8f;
    float S = 255.f / a_c;
    float mu = d_mu[b * 8 + blockIdx.y];
    float rs = d_rs[b * 8 + blockIdx.y];

#pragma unroll
    for (int i = 0; i < 4; i++) {
        int cl = ty + i * 8;
        int c = c0 + cl;
        float v = x[((size_t)b * C_ + c) * HW_ + p0 + tx];
        float xn = (v - mu) * rs * gamma[c] + beta[c];
        float r = fmaxf(xn, 0.f);
        float h = r * r;
        float yv = fminf(h, a_c);
        tile[cl][tx] = (unsigned char)(int)rintf(yv * S);
    }
    __syncthreads();
#pragma unroll
    for (int i = 0; i < 4; i++) {
        int p = p0 + ty + i * 8;           // valid pixel 0..3135
        int y = p / 56, xx = p - y * 56;
        size_t q = (size_t)(y + 1) * 60 + (xx + 1);
        d_hq[((size_t)b * QROWS + q) * 256 + c0 + tx] = tile[tx][ty + i * 8];
    }
}

// ---------------- kernel 3: ternarize weights -> s8 [tap][oc][ic] ----------------
__global__ void tern_kernel(const float* __restrict__ w,
                            const float* __restrict__ a_ptr) {
    int oc = blockIdx.x, tid = threadIdx.x;
    const float* wp = w + (size_t)oc * 2304;
    __shared__ float red[256], red2[256];
    __shared__ float t_sh;

    float s = 0.f;
    for (int i = tid; i < 2304; i += 256) s += fabsf(wp[i]);
    red[tid] = s;
    __syncthreads();
    for (int o = 128; o; o >>= 1) {
        if (tid < o) red[tid] += red[tid + o];
        __syncthreads();
    }
    if (tid == 0) t_sh = 0.05f * red[0] / 2304.0f;
    __syncthreads();
    float t = t_sh;

    float sa = 0.f, sm = 0.f;
    for (int i = tid; i < 2304; i += 256) {
        float aw = fabsf(wp[i]);
        if (aw > t) { sa += aw; sm += 1.f; }
    }
    red[tid] = sa; red2[tid] = sm;
    __syncthreads();
    for (int o = 128; o; o >>= 1) {
        if (tid < o) { red[tid] += red[tid + o]; red2[tid] += red2[tid + o]; }
        __syncthreads();
    }
    if (tid == 0) {
        float alpha = red[0] / (red2[0] + 1e-8f);
        float a_c = fmaxf(a_ptr[0], 0.f) + 1e-8f;
        d_scale[oc] = alpha * a_c / 255.0f;
    }
    for (int i = tid; i < 2304; i += 256) {
        float wv = wp[i];
        signed char q = (fabsf(wv) > t) ? (wv > 0.f ? (signed char)1 : (signed char)-1)
                                        : (signed char)0;
        int ic = i / 9, k = i - ic * 9;    // tap = ky*3+kx
        d_ws[((size_t)k * 256 + oc) * 256 + ic] = q;
    }
}

// ---------------- kernel 4: IMMA implicit-GEMM conv ----------------
// grid (28, 2, 32): M=128 output pixels (q = oy*60+ox), N=128 oc, K=2304 = 36 chunks of 64.
// smem: 4 stages x (A 128x80 + B 128x80) = 81920 B; epilogue reuses as int[128][132].
// occ target: 2 CTAs/SM (160KB smem, <=128 regs/thread).
#define NST 4
#define STAGE_B 20480
#define SMEM_CONV 81920

__global__ void __launch_bounds__(256, 2)
conv_mma_kernel(const float* __restrict__ bias, float* __restrict__ out) {
    extern __shared__ char smem[];
    uint32_t sbase = smem_u32(smem);
    int tid = threadIdx.x;
    int wid = tid >> 5, lane = tid & 31;
    int warp_m = wid >> 2, warp_n = wid & 3;
    int b = blockIdx.z;
    int n0 = blockIdx.y * 128;
    int q0 = blockIdx.x * 128;
    size_t bq0 = (size_t)b * QROWS + q0;

    // cp.async role: threads 0..127 load A row=tid, 128..255 load B row=tid-128
    bool isA = tid < 128;
    int lrow = isA ? tid : tid - 128;
    uint32_t sdst0 = sbase + (isA ? 0u : 10240u) + (uint32_t)lrow * 80u;

    // ldmatrix per-lane offsets
    int grp = lane >> 3, r8 = lane & 7;
    uint32_t aoff[4], boff[4];
#pragma unroll
    for (int t = 0; t < 4; t++)
        aoff[t] = sbase +
            (uint32_t)((warp_m * 64 + t * 16 + (grp & 1) * 8 + r8) * 80 + (grp >> 1) * 16);
    int bl = lane & 15;
#pragma unroll
    for (int u = 0; u < 4; u++)
        boff[u] = sbase + 10240u +
            (uint32_t)((warp_n * 32 + u * 8 + (bl & 7)) * 80 + (bl >> 3) * 16);

    int acc[4][4][4];
#pragma unroll
    for (int t = 0; t < 4; t++)
#pragma unroll
        for (int u = 0; u < 4; u++)
#pragma unroll
            for (int k = 0; k < 4; k++) acc[t][u][k] = 0;

    // stage issue: output pixel q reads padded input pixel q + ky*60 + kx
    auto issue = [&](int s) {
        int st = s & (NST - 1);
        int tap = s >> 2, cc = s & 3;
        int ky = tap / 3, kx = tap - ky * 3;
        const char* g;
        if (isA)
            g = (const char*)(d_hq + (bq0 + (size_t)(ky * 60 + kx + lrow)) * 256 + cc * 64);
        else
            g = (const char*)(d_ws + ((size_t)(tap * 256 + n0 + lrow)) * 256 + cc * 64);
        uint32_t d = sdst0 + (uint32_t)st * STAGE_B;
        CP16(d, g); CP16(d + 16, g + 16); CP16(d + 32, g + 32); CP16(d + 48, g + 48);
        CP_COMMIT();
    };

    issue(0); issue(1); issue(2);

#pragma unroll 1
    for (int s = 0; s < 36; s++) {
        int st = s & (NST - 1);
        CP_WAIT2();
        __syncthreads();
        // early issue: stage (s+3)&3 == (s-1)&3 was fully consumed before this
        // barrier, so refill it NOW and let the loads fly under this stage's MMAs.
        if (s + 3 < 36) issue(s + 3);
        else CP_COMMIT();                 // empty group keeps wait_group accounting aligned
        uint32_t so = (uint32_t)st * STAGE_B;
#pragma unroll
        for (int ks = 0; ks < 2; ks++) {
            uint32_t kb = so + ks * 32;
            uint32_t afr[4][4], bfr[4][2];
#pragma unroll
            for (int t = 0; t < 4; t++) ldsm4(afr[t], aoff[t] + kb);
#pragma unroll
            for (int u = 0; u < 4; u++) ldsm2(bfr[u], boff[u] + kb);
#pragma unroll
            for (int t = 0; t < 4; t++)
#pragma unroll
                for (int u = 0; u < 4; u++)
                    mma_u8s8(acc[t][u], afr[t], bfr[u]);
        }
    }

    // ---------------- epilogue: stage via smem, coalesced NCHW stores ----------------
    // q = q0 + m is the OUTPUT pixel at valid coords (y = q/60, x = q%60),
    // valid iff y < 56 && x < 56 (matches A offset convention q + ky*60 + kx).
    __syncthreads();
    int* sep = (int*)smem;                // [128 oc][pitch 132]
#pragma unroll
    for (int t = 0; t < 4; t++) {
        int m = warp_m * 64 + t * 16 + (lane >> 2);
#pragma unroll
        for (int u = 0; u < 4; u++) {
            int n = warp_n * 32 + u * 8 + 2 * (lane & 3);
            sep[n * 132 + m]           = acc[t][u][0];
            sep[(n + 1) * 132 + m]     = acc[t][u][1];
            sep[n * 132 + m + 8]       = acc[t][u][2];
            sep[(n + 1) * 132 + m + 8] = acc[t][u][3];
        }
    }
    __syncthreads();

#pragma unroll 1
    for (int i = 0; i < 16; i++) {
        int ol = wid + i * 8;
        int oc = n0 + ol;
        float sc = d_scale[oc];
        float bv = __ldg(&bias[oc]);
        float* orow = out + ((size_t)(b * OC_ + oc)) * HW_;
#pragma unroll
        for (int qc = 0; qc < 4; qc++) {
            int m = qc * 32 + lane;
            int q = q0 + m;
            int y = q / 60, x = q - y * 60;
            if (y < 56 && x < 56)
                orow[y * 56 + x] = fmaf(sc, (float)sep[ol * 132 + m], bv);
        }
    }
}

// ---------------- launch ----------------
extern "C" void kernel_launch(void* const* d_in, const int* in_sizes, int n_in,
                              void* d_out, int out_size) {
    const float* x     = (const float*)d_in[0];
    const float* gamma = (const float*)d_in[1];
    const float* beta  = (const float*)d_in[2];
    const float* a     = (const float*)d_in[3];
    const float* wfp   = (const float*)d_in[4];
    const float* bias  = (const float*)d_in[5];
    float* out = (float*)d_out;
    (void)in_sizes; (void)n_in; (void)out_size;

    gn_stats_kernel<<<B_ * 8, 256>>>(x);
    pad_zero_kernel<<<dim3(QROWS, B_ + 1), 64>>>();
    quant_kernel<<<dim3(HW_ / 32, C_ / 32, B_), dim3(32, 8)>>>(x, gamma, beta, a);
    tern_kernel<<<OC_, 256>>>(wfp, a);

    cudaFuncSetAttribute(conv_mma_kernel,
                         cudaFuncAttributeMaxDynamicSharedMemorySize, SMEM_CONV);
    conv_mma_kernel<<<dim3(28, 2, B_), 256, SMEM_CONV>>>(bias, out);
}

// round 7
// speedup vs baseline: 2.1838x; 1.0372x over previous
#include <cuda_runtime.h>
#include <cstdint>
#include <cstddef>

#define B_   32
#define C_   256
#define H_   56
#define W_   56
#define HW_  3136
#define OC_  256
#define QROWS 3600                         // 60x60 padded pixel space per batch

// ---------------- scratch (device globals) ----------------
__device__ float d_mu[B_ * 8];
__device__ float d_rs[B_ * 8];
__device__ float d_scale[OC_];             // alpha_oc * a_c / 255
__device__ unsigned char d_hq[((size_t)B_ * QROWS + 128) * 256];  // padded NHWC u8 (+tail pad)
__device__ signed char  d_ws[9 * 256 * 256];                      // [tap][oc][ic] in {-1,0,1}

// ======================= PTX helpers =======================
__device__ __forceinline__ uint32_t smem_u32(const void* p) {
    uint32_t a;
    asm("{ .reg .u64 t; cvta.to.shared.u64 t, %1; cvt.u32.u64 %0, t; }" : "=r"(a) : "l"(p));
    return a;
}
#define CP16(dst, src) \
    asm volatile("cp.async.cg.shared.global [%0], [%1], 16;" :: "r"(dst), "l"(src) : "memory")
#define CP_COMMIT() asm volatile("cp.async.commit_group;" ::: "memory")
#define CP_WAIT3()  asm volatile("cp.async.wait_group 3;" ::: "memory")

__device__ __forceinline__ void ldsm4(uint32_t* r, uint32_t addr) {
    asm volatile("ldmatrix.sync.aligned.m8n8.x4.shared.b16 {%0,%1,%2,%3}, [%4];"
                 : "=r"(r[0]), "=r"(r[1]), "=r"(r[2]), "=r"(r[3]) : "r"(addr));
}
__device__ __forceinline__ void ldsm2(uint32_t* r, uint32_t addr) {
    asm volatile("ldmatrix.sync.aligned.m8n8.x2.shared.b16 {%0,%1}, [%2];"
                 : "=r"(r[0]), "=r"(r[1]) : "r"(addr));
}
__device__ __forceinline__ void mma_u8s8(int* c, const uint32_t* a, const uint32_t* b) {
    asm volatile(
        "mma.sync.aligned.m16n8k32.row.col.s32.u8.s8.s32 "
        "{%0,%1,%2,%3}, {%4,%5,%6,%7}, {%8,%9}, {%0,%1,%2,%3};"
        : "+r"(c[0]), "+r"(c[1]), "+r"(c[2]), "+r"(c[3])
        : "r"(a[0]), "r"(a[1]), "r"(a[2]), "r"(a[3]), "r"(b[0]), "r"(b[1]));
}

// ---------------- kernel 1: GroupNorm statistics ----------------
__global__ void gn_stats_kernel(const float* __restrict__ x) {
    int bg = blockIdx.x;
    int b = bg >> 3, g = bg & 7;
    const float4* xp = (const float4*)(x + ((size_t)b * C_ + (size_t)g * 32) * HW_);
    const int N4 = 32 * HW_ / 4;           // 25088
    int tid = threadIdx.x;
    float s = 0.f, s2 = 0.f;
#pragma unroll 4
    for (int i = tid; i < N4; i += 512) {
        float4 v = xp[i];
        s += v.x + v.y + v.z + v.w;
        s2 += v.x * v.x + v.y * v.y + v.z * v.z + v.w * v.w;
    }
    __shared__ float r1[512], r2[512];
    r1[tid] = s; r2[tid] = s2;
    __syncthreads();
    for (int o = 256; o; o >>= 1) {
        if (tid < o) { r1[tid] += r1[tid + o]; r2[tid] += r2[tid + o]; }
        __syncthreads();
    }
    if (tid == 0) {
        const float N = (float)(32 * HW_);
        float mu = r1[0] / N;
        float var = r2[0] / N - mu * mu;
        d_mu[bg] = mu;
        d_rs[bg] = rsqrtf(var + 1e-5f);
    }
}

// ---------------- kernel 1b: zero padding rows of d_hq ----------------
__global__ void pad_zero_kernel() {
    int p = blockIdx.x, b = blockIdx.y;
    if (b == B_) {                              // tail overread pad rows
        if (p < 128)
            ((uint32_t*)(d_hq + ((size_t)B_ * QROWS + p) * 256))[threadIdx.x] = 0u;
        return;
    }
    int y = p / 60, x = p - y * 60;
    if (y == 0 || y >= 57 || x == 0 || x >= 57)
        ((uint32_t*)(d_hq + ((size_t)b * QROWS + p) * 256))[threadIdx.x] = 0u;
}

// ---------------- kernel 2: GN + ReLU^2 + PACT quant -> padded NHWC u8 ----------------
__global__ void quant_kernel(const float* __restrict__ x,
                             const float* __restrict__ gamma,
                             const float* __restrict__ beta,
                             const float* __restrict__ a_ptr) {
    __shared__ unsigned char tile[32][33];
    int b = blockIdx.z;
    int c0 = blockIdx.y * 32;
    int p0 = blockIdx.x * 32;
    int tx = threadIdx.x, ty = threadIdx.y;

    float a_c = fmaxf(a_ptr[0], 0.f) + 1e-8f;
    float S = 255.f / a_c;
    float mu = d_mu[b * 8 + blockIdx.y];
    float rs = d_rs[b * 8 + blockIdx.y];

#pragma unroll
    for (int i = 0; i < 4; i++) {
        int cl = ty + i * 8;
        int c = c0 + cl;
        float v = x[((size_t)b * C_ + c) * HW_ + p0 + tx];
        float xn = (v - mu) * rs * gamma[c] + beta[c];
        float r = fmaxf(xn, 0.f);
        float h = r * r;
        float yv = fminf(h, a_c);
        tile[cl][tx] = (unsigned char)(int)rintf(yv * S);
    }
    __syncthreads();
#pragma unroll
    for (int i = 0; i < 4; i++) {
        int p = p0 + ty + i * 8;           // valid pixel 0..3135
        int y = p / 56, xx = p - y * 56;
        size_t q = (size_t)(y + 1) * 60 + (xx + 1);
        d_hq[((size_t)b * QROWS + q) * 256 + c0 + tx] = tile[tx][ty + i * 8];
    }
}

// ---------------- kernel 3: ternarize weights -> s8 [tap][oc][ic] ----------------
__global__ void tern_kernel(const float* __restrict__ w,
                            const float* __restrict__ a_ptr) {
    int oc = blockIdx.x, tid = threadIdx.x;
    const float* wp = w + (size_t)oc * 2304;
    __shared__ float red[256], red2[256];
    __shared__ float t_sh;

    float s = 0.f;
    for (int i = tid; i < 2304; i += 256) s += fabsf(wp[i]);
    red[tid] = s;
    __syncthreads();
    for (int o = 128; o; o >>= 1) {
        if (tid < o) red[tid] += red[tid + o];
        __syncthreads();
    }
    if (tid == 0) t_sh = 0.05f * red[0] / 2304.0f;
    __syncthreads();
    float t = t_sh;

    float sa = 0.f, sm = 0.f;
    for (int i = tid; i < 2304; i += 256) {
        float aw = fabsf(wp[i]);
        if (aw > t) { sa += aw; sm += 1.f; }
    }
    red[tid] = sa; red2[tid] = sm;
    __syncthreads();
    for (int o = 128; o; o >>= 1) {
        if (tid < o) { red[tid] += red[tid + o]; red2[tid] += red2[tid + o]; }
        __syncthreads();
    }
    if (tid == 0) {
        float alpha = red[0] / (red2[0] + 1e-8f);
        float a_c = fmaxf(a_ptr[0], 0.f) + 1e-8f;
        d_scale[oc] = alpha * a_c / 255.0f;
    }
    for (int i = tid; i < 2304; i += 256) {
        float wv = wp[i];
        signed char q = (fabsf(wv) > t) ? (wv > 0.f ? (signed char)1 : (signed char)-1)
                                        : (signed char)0;
        int ic = i / 9, k = i - ic * 9;    // tap = ky*3+kx
        d_ws[((size_t)k * 256 + oc) * 256 + ic] = q;
    }
}

// ---------------- kernel 4: IMMA implicit-GEMM conv ----------------
// grid (27, 2, 32): M=128 output pixels (q = oy*60+ox), N=128 oc, K=2304 = 36 chunks of 64.
// smem: 5 stages x (A 128x80 + B 128x80) = 102400 B; epilogue reuses as int[128][132].
// occ: 2 CTAs/SM (204.8KB smem), <=128 regs/thread.
#define NST 5
#define STAGE_B 20480
#define SMEM_CONV (NST * STAGE_B)

__global__ void __launch_bounds__(256, 2)
conv_mma_kernel(const float* __restrict__ bias, float* __restrict__ out) {
    extern __shared__ char smem[];
    uint32_t sbase = smem_u32(smem);
    int tid = threadIdx.x;
    int wid = tid >> 5, lane = tid & 31;
    int warp_m = wid >> 2, warp_n = wid & 3;
    int b = blockIdx.z;
    int n0 = blockIdx.y * 128;
    int q0 = blockIdx.x * 128;
    size_t bq0 = (size_t)b * QROWS + q0;

    // cp.async role: threads 0..127 load A row=tid, 128..255 load B row=tid-128
    bool isA = tid < 128;
    int lrow = isA ? tid : tid - 128;
    uint32_t sdst0 = sbase + (isA ? 0u : 10240u) + (uint32_t)lrow * 80u;

    // ldmatrix per-lane offsets
    int grp = lane >> 3, r8 = lane & 7;
    uint32_t aoff[4], boff[4];
#pragma unroll
    for (int t = 0; t < 4; t++)
        aoff[t] = sbase +
            (uint32_t)((warp_m * 64 + t * 16 + (grp & 1) * 8 + r8) * 80 + (grp >> 1) * 16);
    int bl = lane & 15;
#pragma unroll
    for (int u = 0; u < 4; u++)
        boff[u] = sbase + 10240u +
            (uint32_t)((warp_n * 32 + u * 8 + (bl & 7)) * 80 + (bl >> 3) * 16);

    int acc[4][4][4];
#pragma unroll
    for (int t = 0; t < 4; t++)
#pragma unroll
        for (int u = 0; u < 4; u++)
#pragma unroll
            for (int k = 0; k < 4; k++) acc[t][u][k] = 0;

    // stage issue: output pixel q reads padded input pixel q + ky*60 + kx
    auto issue = [&](int s) {
        int st = s % NST;
        int tap = s >> 2, cc = s & 3;
        int ky = tap / 3, kx = tap - ky * 3;
        const char* g;
        if (isA)
            g = (const char*)(d_hq + (bq0 + (size_t)(ky * 60 + kx + lrow)) * 256 + cc * 64);
        else
            g = (const char*)(d_ws + ((size_t)(tap * 256 + n0 + lrow)) * 256 + cc * 64);
        uint32_t d = sdst0 + (uint32_t)st * STAGE_B;
        CP16(d, g); CP16(d + 16, g + 16); CP16(d + 32, g + 32); CP16(d + 48, g + 48);
        CP_COMMIT();
    };

    issue(0); issue(1); issue(2); issue(3);

#pragma unroll 1
    for (int s = 0; s < 36; s++) {
        int st = s % NST;
        CP_WAIT3();
        __syncthreads();
        // refill stage (s+4)%5 == (s-1)%5: fully consumed before this barrier.
        if (s + 4 < 36) issue(s + 4);
        else CP_COMMIT();                 // empty group keeps wait_group accounting aligned
        uint32_t so = (uint32_t)st * STAGE_B;
#pragma unroll
        for (int ks = 0; ks < 2; ks++) {
            uint32_t kb = so + ks * 32;
            uint32_t afr[4][4], bfr[4][2];
#pragma unroll
            for (int t = 0; t < 4; t++) ldsm4(afr[t], aoff[t] + kb);
#pragma unroll
            for (int u = 0; u < 4; u++) ldsm2(bfr[u], boff[u] + kb);
#pragma unroll
            for (int t = 0; t < 4; t++)
#pragma unroll
                for (int u = 0; u < 4; u++)
                    mma_u8s8(acc[t][u], afr[t], bfr[u]);
        }
    }

    // ---------------- epilogue: stage via smem, coalesced NCHW stores ----------------
    // q = q0 + m is the OUTPUT pixel at valid coords (y = q/60, x = q%60),
    // valid iff y < 56 && x < 56 (matches A offset convention q + ky*60 + kx).
    __syncthreads();
    int* sep = (int*)smem;                // [128 oc][pitch 132]
#pragma unroll
    for (int t = 0; t < 4; t++) {
        int m = warp_m * 64 + t * 16 + (lane >> 2);
#pragma unroll
        for (int u = 0; u < 4; u++) {
            int n = warp_n * 32 + u * 8 + 2 * (lane & 3);
            sep[n * 132 + m]           = acc[t][u][0];
            sep[(n + 1) * 132 + m]     = acc[t][u][1];
            sep[n * 132 + m + 8]       = acc[t][u][2];
            sep[(n + 1) * 132 + m + 8] = acc[t][u][3];
        }
    }
    __syncthreads();

#pragma unroll 1
    for (int i = 0; i < 16; i++) {
        int ol = wid + i * 8;
        int oc = n0 + ol;
        float sc = d_scale[oc];
        float bv = __ldg(&bias[oc]);
        float* orow = out + ((size_t)(b * OC_ + oc)) * HW_;
#pragma unroll
        for (int qc = 0; qc < 4; qc++) {
            int m = qc * 32 + lane;
            int q = q0 + m;
            int y = q / 60, x = q - y * 60;
            if (y < 56 && x < 56)
                orow[y * 56 + x] = fmaf(sc, (float)sep[ol * 132 + m], bv);
        }
    }
}

// ---------------- launch ----------------
extern "C" void kernel_launch(void* const* d_in, const int* in_sizes, int n_in,
                              void* d_out, int out_size) {
    const float* x     = (const float*)d_in[0];
    const float* gamma = (const float*)d_in[1];
    const float* beta  = (const float*)d_in[2];
    const float* a     = (const float*)d_in[3];
    const float* wfp   = (const float*)d_in[4];
    const float* bias  = (const float*)d_in[5];
    float* out = (float*)d_out;
    (void)in_sizes; (void)n_in; (void)out_size;

    gn_stats_kernel<<<B_ * 8, 512>>>(x);
    pad_zero_kernel<<<dim3(QROWS, B_ + 1), 64>>>();
    quant_kernel<<<dim3(HW_ / 32, C_ / 32, B_), dim3(32, 8)>>>(x, gamma, beta, a);
    tern_kernel<<<OC_, 256>>>(wfp, a);

    cudaFuncSetAttribute(conv_mma_kernel,
                         cudaFuncAttributeMaxDynamicSharedMemorySize, SMEM_CONV);
    conv_mma_kernel<<<dim3(27, 2, B_), 256, SMEM_CONV>>>(bias, out);
}

// round 8
// speedup vs baseline: 2.3625x; 1.0818x over previous
#include <cuda_runtime.h>
#include <cstdint>
#include <cstddef>

#define B_   32
#define C_   256
#define H_   56
#define W_   56
#define HW_  3136
#define OC_  256
#define PW   58                            // padded width/height
#define PQ   3492                          // 58*58 + 128 tail pad rows

// ---------------- scratch (device globals) ----------------
__device__ float d_mu[B_ * 8];
__device__ float d_rs[B_ * 8];
__device__ float d_scale[OC_];             // alpha_oc * a_c / 255
__device__ unsigned char d_hq[(size_t)B_ * PQ * 256];   // padded NHWC u8
__device__ signed char  d_ws[9 * 256 * 256];            // [tap][oc][ic] in {-1,0,1}

// ======================= PTX helpers =======================
__device__ __forceinline__ uint32_t smem_u32(const void* p) {
    uint32_t a;
    asm("{ .reg .u64 t; cvta.to.shared.u64 t, %1; cvt.u32.u64 %0, t; }" : "=r"(a) : "l"(p));
    return a;
}
#define CP16(dst, src) \
    asm volatile("cp.async.cg.shared.global [%0], [%1], 16;" :: "r"(dst), "l"(src) : "memory")
#define CP_COMMIT() asm volatile("cp.async.commit_group;" ::: "memory")
#define CP_WAIT3()  asm volatile("cp.async.wait_group 3;" ::: "memory")

__device__ __forceinline__ void ldsm4(uint32_t* r, uint32_t addr) {
    asm volatile("ldmatrix.sync.aligned.m8n8.x4.shared.b16 {%0,%1,%2,%3}, [%4];"
                 : "=r"(r[0]), "=r"(r[1]), "=r"(r[2]), "=r"(r[3]) : "r"(addr));
}
__device__ __forceinline__ void ldsm2(uint32_t* r, uint32_t addr) {
    asm volatile("ldmatrix.sync.aligned.m8n8.x2.shared.b16 {%0,%1}, [%2];"
                 : "=r"(r[0]), "=r"(r[1]) : "r"(addr));
}
__device__ __forceinline__ void mma_u8s8(int* c, const uint32_t* a, const uint32_t* b) {
    asm volatile(
        "mma.sync.aligned.m16n8k32.row.col.s32.u8.s8.s32 "
        "{%0,%1,%2,%3}, {%4,%5,%6,%7}, {%8,%9}, {%0,%1,%2,%3};"
        : "+r"(c[0]), "+r"(c[1]), "+r"(c[2]), "+r"(c[3])
        : "r"(a[0]), "r"(a[1]), "r"(a[2]), "r"(a[3]), "r"(b[0]), "r"(b[1]));
}

// ---------------- kernel 1: GroupNorm statistics ----------------
__global__ void gn_stats_kernel(const float* __restrict__ x) {
    int bg = blockIdx.x;
    int b = bg >> 3, g = bg & 7;
    const float4* xp = (const float4*)(x + ((size_t)b * C_ + (size_t)g * 32) * HW_);
    const int N4 = 32 * HW_ / 4;           // 25088
    int tid = threadIdx.x;
    float s = 0.f, s2 = 0.f;
#pragma unroll 4
    for (int i = tid; i < N4; i += 512) {
        float4 v = xp[i];
        s += v.x + v.y + v.z + v.w;
        s2 += v.x * v.x + v.y * v.y + v.z * v.z + v.w * v.w;
    }
    __shared__ float r1[512], r2[512];
    r1[tid] = s; r2[tid] = s2;
    __syncthreads();
    for (int o = 256; o; o >>= 1) {
        if (tid < o) { r1[tid] += r1[tid + o]; r2[tid] += r2[tid + o]; }
        __syncthreads();
    }
    if (tid == 0) {
        const float N = (float)(32 * HW_);
        float mu = r1[0] / N;
        float var = r2[0] / N - mu * mu;
        d_mu[bg] = mu;
        d_rs[bg] = rsqrtf(var + 1e-5f);
    }
}

// ---------------- kernel 1b: zero pad rows of d_hq (range [base, base+1746)) ----
__global__ void pad_zero_kernel(int base) {
    int r = base + blockIdx.x;             // row in [0, PQ)
    int b = blockIdx.y;
    bool pad;
    if (r >= PW * PW) pad = true;          // tail overread rows
    else {
        int py = r / PW, px = r - py * PW;
        pad = (py == 0) | (py == PW - 1) | (px == 0) | (px == PW - 1);
    }
    if (pad)
        ((uint32_t*)(d_hq + ((size_t)b * PQ + r) * 256))[threadIdx.x] = 0u;
}

// ---------------- kernel 2: GN + ReLU^2 + PACT quant -> padded NHWC u8 ----------------
__global__ void quant_kernel(const float* __restrict__ x,
                             const float* __restrict__ gamma,
                             const float* __restrict__ beta,
                             const float* __restrict__ a_ptr) {
    __shared__ unsigned char tile[32][33];
    int b = blockIdx.z;
    int c0 = blockIdx.y * 32;
    int p0 = blockIdx.x * 32;
    int tx = threadIdx.x, ty = threadIdx.y;

    float a_c = fmaxf(a_ptr[0], 0.f) + 1e-8f;
    float S = 255.f / a_c;
    float mu = d_mu[b * 8 + blockIdx.y];
    float rs = d_rs[b * 8 + blockIdx.y];

#pragma unroll
    for (int i = 0; i < 4; i++) {
        int cl = ty + i * 8;
        int c = c0 + cl;
        float v = x[((size_t)b * C_ + c) * HW_ + p0 + tx];
        float xn = (v - mu) * rs * gamma[c] + beta[c];
        float r = fmaxf(xn, 0.f);
        float h = r * r;
        float yv = fminf(h, a_c);
        tile[cl][tx] = (unsigned char)(int)rintf(yv * S);
    }
    __syncthreads();
#pragma unroll
    for (int i = 0; i < 4; i++) {
        int p = p0 + ty + i * 8;           // valid pixel 0..3135
        int y = p / 56, xx = p - y * 56;
        size_t r = (size_t)(y + 1) * PW + (xx + 1);
        d_hq[((size_t)b * PQ + r) * 256 + c0 + tx] = tile[tx][ty + i * 8];
    }
}

// ---------------- kernel 3: ternarize weights -> s8 [tap][oc][ic] ----------------
__global__ void tern_kernel(const float* __restrict__ w,
                            const float* __restrict__ a_ptr) {
    int oc = blockIdx.x, tid = threadIdx.x;
    const float* wp = w + (size_t)oc * 2304;
    __shared__ float red[256], red2[256];
    __shared__ float t_sh;

    float s = 0.f;
    for (int i = tid; i < 2304; i += 256) s += fabsf(wp[i]);
    red[tid] = s;
    __syncthreads();
    for (int o = 128; o; o >>= 1) {
        if (tid < o) red[tid] += red[tid + o];
        __syncthreads();
    }
    if (tid == 0) t_sh = 0.05f * red[0] / 2304.0f;
    __syncthreads();
    float t = t_sh;

    float sa = 0.f, sm = 0.f;
    for (int i = tid; i < 2304; i += 256) {
        float aw = fabsf(wp[i]);
        if (aw > t) { sa += aw; sm += 1.f; }
    }
    red[tid] = sa; red2[tid] = sm;
    __syncthreads();
    for (int o = 128; o; o >>= 1) {
        if (tid < o) { red[tid] += red[tid + o]; red2[tid] += red2[tid + o]; }
        __syncthreads();
    }
    if (tid == 0) {
        float alpha = red[0] / (red2[0] + 1e-8f);
        float a_c = fmaxf(a_ptr[0], 0.f) + 1e-8f;
        d_scale[oc] = alpha * a_c / 255.0f;
    }
    for (int i = tid; i < 2304; i += 256) {
        float wv = wp[i];
        signed char q = (fabsf(wv) > t) ? (wv > 0.f ? (signed char)1 : (signed char)-1)
                                        : (signed char)0;
        int ic = i / 9, k = i - ic * 9;    // tap = ky*3+kx
        d_ws[((size_t)k * 256 + oc) * 256 + ic] = q;
    }
}

// ---------------- kernel 4: IMMA implicit-GEMM conv ----------------
// grid (25, 2, 32): M=128 OUTPUT pixels q=q0..q0+127 (y=q/56, x=q%56), N=128 oc,
// K=2304 = 36 chunks of 64. A row for tap (ky,kx): (y*58+x) + ky*58+kx.
// smem: 5 stages x (A 128x80 + B 128x80) = 102400 B; epilogue reuses as int[128][132].
#define NST 5
#define STAGE_B 20480
#define SMEM_CONV (NST * STAGE_B)

__global__ void __launch_bounds__(256, 2)
conv_mma_kernel(const float* __restrict__ bias, float* __restrict__ out) {
    extern __shared__ char smem[];
    uint32_t sbase = smem_u32(smem);
    int tid = threadIdx.x;
    int wid = tid >> 5, lane = tid & 31;
    int warp_m = wid >> 2, warp_n = wid & 3;
    int b = blockIdx.z;
    int n0 = blockIdx.y * 128;
    int q0 = blockIdx.x * 128;

    // cp.async role: threads 0..127 load A row=tid, 128..255 load B row=tid-128
    bool isA = tid < 128;
    int lrow = isA ? tid : tid - 128;
    uint32_t sdst0 = sbase + (isA ? 0u : 10240u) + (uint32_t)lrow * 80u;

    // A loader base: rowbase = y*58 + x for this thread's output pixel
    const char* gbase;
    if (isA) {
        int q = q0 + lrow;                 // may exceed 3135 on tail tile (pads are zero)
        int y = q / 56, xx = q - y * 56;
        gbase = (const char*)(d_hq + ((size_t)b * PQ + (size_t)(y * PW + xx)) * 256);
    } else {
        gbase = (const char*)(d_ws + (size_t)(n0 + lrow) * 256);
    }

    // ldmatrix per-lane offsets
    int grp = lane >> 3, r8 = lane & 7;
    uint32_t aoff[4], boff[4];
#pragma unroll
    for (int t = 0; t < 4; t++)
        aoff[t] = sbase +
            (uint32_t)((warp_m * 64 + t * 16 + (grp & 1) * 8 + r8) * 80 + (grp >> 1) * 16);
    int bl = lane & 15;
#pragma unroll
    for (int u = 0; u < 4; u++)
        boff[u] = sbase + 10240u +
            (uint32_t)((warp_n * 32 + u * 8 + (bl & 7)) * 80 + (bl >> 3) * 16);

    int acc[4][4][4];
#pragma unroll
    for (int t = 0; t < 4; t++)
#pragma unroll
        for (int u = 0; u < 4; u++)
#pragma unroll
            for (int k = 0; k < 4; k++) acc[t][u][k] = 0;

    // stage issue: s -> tap = s>>2, chunk cc = s&3
    auto issue = [&](int s) {
        int st = s % NST;
        int tap = s >> 2, cc = s & 3;
        const char* g;
        if (isA) {
            int ky = tap / 3, kx = tap - ky * 3;
            g = gbase + (size_t)(ky * PW + kx) * 256 + cc * 64;
        } else {
            g = gbase + (size_t)tap * 65536 + cc * 64;   // [tap][oc][ic]: tap stride 256*256
        }
        uint32_t d = sdst0 + (uint32_t)st * STAGE_B;
        CP16(d, g); CP16(d + 16, g + 16); CP16(d + 32, g + 32); CP16(d + 48, g + 48);
        CP_COMMIT();
    };

    issue(0); issue(1); issue(2); issue(3);

#pragma unroll 1
    for (int s = 0; s < 36; s++) {
        int st = s % NST;
        CP_WAIT3();
        __syncthreads();
        if (s + 4 < 36) issue(s + 4);     // refill stage consumed before this barrier
        else CP_COMMIT();                 // empty group keeps wait accounting aligned
        uint32_t so = (uint32_t)st * STAGE_B;
#pragma unroll
        for (int ks = 0; ks < 2; ks++) {
            uint32_t kb = so + ks * 32;
            uint32_t afr[4][4], bfr[4][2];
#pragma unroll
            for (int t = 0; t < 4; t++) ldsm4(afr[t], aoff[t] + kb);
#pragma unroll
            for (int u = 0; u < 4; u++) ldsm2(bfr[u], boff[u] + kb);
#pragma unroll
            for (int t = 0; t < 4; t++)
#pragma unroll
                for (int u = 0; u < 4; u++)
                    mma_u8s8(acc[t][u], afr[t], bfr[u]);
        }
    }

    // ---------------- epilogue: stage via smem, fully coalesced NCHW stores --------
    __syncthreads();
    int* sep = (int*)smem;                // [128 oc][pitch 132]
#pragma unroll
    for (int t = 0; t < 4; t++) {
        int m = warp_m * 64 + t * 16 + (lane >> 2);
#pragma unroll
        for (int u = 0; u < 4; u++) {
            int n = warp_n * 32 + u * 8 + 2 * (lane & 3);
            sep[n * 132 + m]           = acc[t][u][0];
            sep[(n + 1) * 132 + m]     = acc[t][u][1];
            sep[n * 132 + m + 8]       = acc[t][u][2];
            sep[(n + 1) * 132 + m + 8] = acc[t][u][3];
        }
    }
    __syncthreads();

#pragma unroll 1
    for (int i = 0; i < 16; i++) {
        int ol = wid + i * 8;
        int oc = n0 + ol;
        float sc = d_scale[oc];
        float bv = __ldg(&bias[oc]);
        float* orow = out + ((size_t)(b * OC_ + oc)) * HW_ + q0;
#pragma unroll
        for (int qc = 0; qc < 4; qc++) {
            int m = qc * 32 + lane;
            if (q0 + m < HW_)
                orow[m] = fmaf(sc, (float)sep[ol * 132 + m], bv);
        }
    }
}

// ---------------- launch (conv is the 6th launch -> captured by ncu -s 5 -c 1) ----
extern "C" void kernel_launch(void* const* d_in, const int* in_sizes, int n_in,
                              void* d_out, int out_size) {
    const float* x     = (const float*)d_in[0];
    const float* gamma = (const float*)d_in[1];
    const float* beta  = (const float*)d_in[2];
    const float* a     = (const float*)d_in[3];
    const float* wfp   = (const float*)d_in[4];
    const float* bias  = (const float*)d_in[5];
    float* out = (float*)d_out;
    (void)in_sizes; (void)n_in; (void)out_size;

    gn_stats_kernel<<<B_ * 8, 512>>>(x);
    pad_zero_kernel<<<dim3(PQ / 2, B_), 64>>>(0);
    pad_zero_kernel<<<dim3(PQ / 2, B_), 64>>>(PQ / 2);
    quant_kernel<<<dim3(HW_ / 32, C_ / 32, B_), dim3(32, 8)>>>(x, gamma, beta, a);
    tern_kernel<<<OC_, 256>>>(wfp, a);

    cudaFuncSetAttribute(conv_mma_kernel,
                         cudaFuncAttributeMaxDynamicSharedMemorySize, SMEM_CONV);
    conv_mma_kernel<<<dim3(25, 2, B_), 256, SMEM_CONV>>>(bias, out);
}

// round 9
// speedup vs baseline: 2.7619x; 1.1691x over previous
#include <cuda_runtime.h>
#include <cstdint>
#include <cstddef>

#define B_   32
#define C_   256
#define HW_  3136
#define OC_  256
#define PW   58                            // padded width/height
#define PQ   3492                          // 58*58 + 128 tail pad rows

// ---------------- scratch (device globals) ----------------
__device__ float d_mu[B_ * 8];
__device__ float d_rs[B_ * 8];
__device__ float d_scale[OC_];             // alpha_oc * a_c / 255
__device__ unsigned char d_hq[(size_t)B_ * PQ * 256];   // padded NHWC u8
__device__ signed char  d_ws[9 * 256 * 256];            // [tap][oc][ic] in {-1,0,1}

// ======================= PTX helpers =======================
__device__ __forceinline__ uint32_t smem_u32(const void* p) {
    uint32_t a;
    asm("{ .reg .u64 t; cvta.to.shared.u64 t, %1; cvt.u32.u64 %0, t; }" : "=r"(a) : "l"(p));
    return a;
}
#define CP16(dst, src) \
    asm volatile("cp.async.cg.shared.global [%0], [%1], 16;" :: "r"(dst), "l"(src) : "memory")
#define CP_COMMIT() asm volatile("cp.async.commit_group;" ::: "memory")
#define CP_WAIT3()  asm volatile("cp.async.wait_group 3;" ::: "memory")

__device__ __forceinline__ void ldsm4(uint32_t* r, uint32_t addr) {
    asm volatile("ldmatrix.sync.aligned.m8n8.x4.shared.b16 {%0,%1,%2,%3}, [%4];"
                 : "=r"(r[0]), "=r"(r[1]), "=r"(r[2]), "=r"(r[3]) : "r"(addr));
}
__device__ __forceinline__ void ldsm2(uint32_t* r, uint32_t addr) {
    asm volatile("ldmatrix.sync.aligned.m8n8.x2.shared.b16 {%0,%1}, [%2];"
                 : "=r"(r[0]), "=r"(r[1]) : "r"(addr));
}
__device__ __forceinline__ void mma_u8s8(int* c, const uint32_t* a, const uint32_t* b) {
    asm volatile(
        "mma.sync.aligned.m16n8k32.row.col.s32.u8.s8.s32 "
        "{%0,%1,%2,%3}, {%4,%5,%6,%7}, {%8,%9}, {%0,%1,%2,%3};"
        : "+r"(c[0]), "+r"(c[1]), "+r"(c[2]), "+r"(c[3])
        : "r"(a[0]), "r"(a[1]), "r"(a[2]), "r"(a[3]), "r"(b[0]), "r"(b[1]));
}
__device__ __forceinline__ int dp4a_us(unsigned a, unsigned b, int c) {
    int d;
    asm("dp4a.u32.s32 %0, %1, %2, %3;" : "=r"(d) : "r"(a), "r"(b), "r"(c));
    return d;
}

// ---------------- kernel 1: ternarize weights -> s8 [tap][oc][ic] ----------------
__global__ void tern_kernel(const float* __restrict__ w,
                            const float* __restrict__ a_ptr) {
    int oc = blockIdx.x, tid = threadIdx.x;
    const float* wp = w + (size_t)oc * 2304;
    __shared__ float red[256], red2[256];
    __shared__ float t_sh;

    float s = 0.f;
    for (int i = tid; i < 2304; i += 256) s += fabsf(wp[i]);
    red[tid] = s;
    __syncthreads();
    for (int o = 128; o; o >>= 1) {
        if (tid < o) red[tid] += red[tid + o];
        __syncthreads();
    }
    if (tid == 0) t_sh = 0.05f * red[0] / 2304.0f;
    __syncthreads();
    float t = t_sh;

    float sa = 0.f, sm = 0.f;
    for (int i = tid; i < 2304; i += 256) {
        float aw = fabsf(wp[i]);
        if (aw > t) { sa += aw; sm += 1.f; }
    }
    red[tid] = sa; red2[tid] = sm;
    __syncthreads();
    for (int o = 128; o; o >>= 1) {
        if (tid < o) { red[tid] += red[tid + o]; red2[tid] += red2[tid + o]; }
        __syncthreads();
    }
    if (tid == 0) {
        float alpha = red[0] / (red2[0] + 1e-8f);
        float a_c = fmaxf(a_ptr[0], 0.f) + 1e-8f;
        d_scale[oc] = alpha * a_c / 255.0f;
    }
    for (int i = tid; i < 2304; i += 256) {
        float wv = wp[i];
        signed char q = (fabsf(wv) > t) ? (wv > 0.f ? (signed char)1 : (signed char)-1)
                                        : (signed char)0;
        int ic = i / 9, k = i - ic * 9;    // tap = ky*3+kx
        d_ws[((size_t)k * 256 + oc) * 256 + ic] = q;
    }
}

// ---------------- kernel 2: GroupNorm statistics ----------------
__global__ void gn_stats_kernel(const float* __restrict__ x) {
    int bg = blockIdx.x;
    int b = bg >> 3, g = bg & 7;
    const float4* xp = (const float4*)(x + ((size_t)b * C_ + (size_t)g * 32) * HW_);
    const int N4 = 32 * HW_ / 4;
    int tid = threadIdx.x;
    float s = 0.f, s2 = 0.f;
#pragma unroll 4
    for (int i = tid; i < N4; i += 512) {
        float4 v = xp[i];
        s += v.x + v.y + v.z + v.w;
        s2 += v.x * v.x + v.y * v.y + v.z * v.z + v.w * v.w;
    }
    __shared__ float r1[512], r2[512];
    r1[tid] = s; r2[tid] = s2;
    __syncthreads();
    for (int o = 256; o; o >>= 1) {
        if (tid < o) { r1[tid] += r1[tid + o]; r2[tid] += r2[tid + o]; }
        __syncthreads();
    }
    if (tid == 0) {
        const float N = (float)(32 * HW_);
        float mu = r1[0] / N;
        float var = r2[0] / N - mu * mu;
        d_mu[bg] = mu;
        d_rs[bg] = rsqrtf(var + 1e-5f);
    }
}

// ---------------- kernel 3: GN + ReLU^2 + PACT quant + pad-zero (fused) ----------
// grid (110, 8, 32): x<98 quantize 32x32 tiles; x>=98 (y==0) zero pad rows.
__global__ void quant_kernel(const float* __restrict__ x,
                             const float* __restrict__ gamma,
                             const float* __restrict__ beta,
                             const float* __restrict__ a_ptr) {
    int b = blockIdx.z;
    int tx = threadIdx.x, ty = threadIdx.y;
    int tid = ty * 32 + tx;

    if (blockIdx.x >= 98) {                // pad-zero blocks
        if (blockIdx.y != 0) return;
        int slot = (blockIdx.x - 98) * 30 + (tid >> 3);
        if (slot >= 356) return;
        int r;
        if (slot < 58)        r = slot;                      // y=0
        else if (slot < 116)  r = 3306 + (slot - 58);        // y=57
        else if (slot < 172)  r = (slot - 115) * PW;         // x=0, y=1..56
        else if (slot < 228)  r = (slot - 171) * PW + 57;    // x=57, y=1..56
        else                  r = 3364 + (slot - 228);       // tail overread rows
        uint4* dst = (uint4*)(d_hq + ((size_t)b * PQ + r) * 256 + (tid & 7) * 32);
        dst[0] = make_uint4(0, 0, 0, 0);
        dst[1] = make_uint4(0, 0, 0, 0);
        return;
    }

    __shared__ unsigned char tile[32][33];
    int c0 = blockIdx.y * 32;
    int p0 = blockIdx.x * 32;

    float a_c = fmaxf(a_ptr[0], 0.f) + 1e-8f;
    float S = 255.f / a_c;
    float mu = d_mu[b * 8 + blockIdx.y];
    float rs = d_rs[b * 8 + blockIdx.y];

#pragma unroll
    for (int i = 0; i < 4; i++) {
        int cl = ty + i * 8;
        int c = c0 + cl;
        float v = x[((size_t)b * C_ + c) * HW_ + p0 + tx];
        float xn = (v - mu) * rs * gamma[c] + beta[c];
        float r = fmaxf(xn, 0.f);
        float h = r * r;
        float yv = fminf(h, a_c);
        tile[cl][tx] = (unsigned char)(int)rintf(yv * S);
    }
    __syncthreads();
#pragma unroll
    for (int i = 0; i < 4; i++) {
        int p = p0 + ty + i * 8;           // valid pixel 0..3135
        int y = p / 56, xx = p - y * 56;
        size_t r = (size_t)(y + 1) * PW + (xx + 1);
        d_hq[((size_t)b * PQ + r) * 256 + c0 + tx] = tile[tx][ty + i * 8];
    }
}

// ---------------- kernel 4: hybrid IMMA + dp4a implicit-GEMM conv ----------------
// 1600 CTAs flat: unit = bid -> (b, n-tile, m-tile). Role: (bid&15)<9 -> IMMA
// (tensor pipe), else dp4a (fma/alu pipes). Same cp.async pipeline for both.
// smem rows: pitch 80B, 64B payload as 4x16B chunks stored at (c ^ (row>>3))&3.
#define NST 5
#define STAGE_B 20480
#define SMEM_CONV (NST * STAGE_B)

__global__ void __launch_bounds__(256, 2)
conv_mma_kernel(const float* __restrict__ bias, float* __restrict__ out) {
    extern __shared__ char smem[];
    uint32_t sbase = smem_u32(smem);
    int tid = threadIdx.x;
    int wid = tid >> 5, lane = tid & 31;
    int bid = blockIdx.x;
    int b = bid / 50;
    int rem = bid - b * 50;
    int n0 = (rem / 25) * 128;
    int q0 = (rem % 25) * 128;
    bool isIMMA = (bid & 15) < 9;

    // cp.async loaders: threads 0..127 A row=tid, 128..255 B row=tid-128
    bool isA = tid < 128;
    int lrow = isA ? tid : tid - 128;
    int lsw = (lrow >> 3) & 3;             // store-side swizzle key
    uint32_t sdst0 = sbase + (isA ? 0u : 10240u) + (uint32_t)lrow * 80u;

    const char* gbase;
    if (isA) {
        int q = q0 + lrow;                 // tail tiles read zeroed pad rows
        int y = q / 56, xx = q - y * 56;
        gbase = (const char*)(d_hq + ((size_t)b * PQ + (size_t)(y * PW + xx)) * 256);
    } else {
        gbase = (const char*)(d_ws + (size_t)(n0 + lrow) * 256);
    }

    auto issue = [&](int s) {
        int st = s % NST;
        int tap = s >> 2, cc = s & 3;
        const char* g;
        if (isA) {
            int ky = tap / 3, kx = tap - ky * 3;
            g = gbase + (size_t)(ky * PW + kx) * 256 + cc * 64;
        } else {
            g = gbase + (size_t)tap * 65536 + cc * 64;
        }
        uint32_t d = sdst0 + (uint32_t)st * STAGE_B;
        CP16(d + ((0 ^ lsw) & 3) * 16, g);
        CP16(d + ((1 ^ lsw) & 3) * 16, g + 16);
        CP16(d + ((2 ^ lsw) & 3) * 16, g + 32);
        CP16(d + ((3 ^ lsw) & 3) * 16, g + 48);
        CP_COMMIT();
    };

    // shared accumulators (64 regs, disjoint role lifetimes)
    int acc[64];
#pragma unroll
    for (int i = 0; i < 64; i++) acc[i] = 0;

    // ---- IMMA per-lane read geometry ----
    int warp_m = wid >> 2, warp_n = wid & 3;
    int grp = lane >> 3, r8 = lane & 7;
    uint32_t a_base[4]; int a_swz[4]; int a_cb = grp >> 1;
#pragma unroll
    for (int t = 0; t < 4; t++) {
        int row = warp_m * 64 + t * 16 + (grp & 1) * 8 + r8;
        a_base[t] = sbase + (uint32_t)row * 80u;
        a_swz[t] = (row >> 3) & 3;
    }
    int bl = lane & 15;
    uint32_t b_base[4]; int b_swz[4]; int b_cb = bl >> 3;
#pragma unroll
    for (int u = 0; u < 4; u++) {
        int row = warp_n * 32 + u * 8 + (bl & 7);
        b_base[u] = sbase + 10240u + (uint32_t)row * 80u;
        b_swz[u] = (row >> 3) & 3;
    }

    // ---- dp4a thread geometry ----
    int tm = tid >> 4, tn = tid & 15;      // 8 pixels x 8 ocs per thread
    const char* sA = smem;                 // A rows at pitch 80
    const char* sB = smem + 10240;

    issue(0); issue(1); issue(2); issue(3);

#pragma unroll 1
    for (int s = 0; s < 36; s++) {
        int st = s % NST;
        CP_WAIT3();
        __syncthreads();
        if (s + 4 < 36) issue(s + 4);
        else CP_COMMIT();
        uint32_t so = (uint32_t)st * STAGE_B;

        if (isIMMA) {
#pragma unroll
            for (int ks = 0; ks < 2; ks++) {
                uint32_t afr[4][4], bfr[4][2];
#pragma unroll
                for (int t = 0; t < 4; t++) {
                    uint32_t c = (uint32_t)(((ks * 2 + a_cb) ^ a_swz[t]) & 3) * 16u;
                    ldsm4(afr[t], a_base[t] + so + c);
                }
#pragma unroll
                for (int u = 0; u < 4; u++) {
                    uint32_t c = (uint32_t)(((ks * 2 + b_cb) ^ b_swz[u]) & 3) * 16u;
                    ldsm2(bfr[u], b_base[u] + so + c);
                }
#pragma unroll
                for (int t = 0; t < 4; t++)
#pragma unroll
                    for (int u = 0; u < 4; u++)
                        mma_u8s8(&acc[(t * 4 + u) * 4], afr[t], bfr[u]);
            }
        } else {
            const char* pA = sA + so;
            const char* pB = sB + so;
#pragma unroll 1
            for (int kb = 0; kb < 4; kb++) {
                uint32_t ca = (uint32_t)((kb ^ tm) & 3) * 16u;   // m>>3 == tm
                uint32_t cb = (uint32_t)((kb ^ tn) & 3) * 16u;   // n>>3 == tn
                uint4 av[8];
#pragma unroll
                for (int i = 0; i < 8; i++)
                    av[i] = *(const uint4*)(pA + (tm * 8 + i) * 80 + ca);
#pragma unroll
                for (int j = 0; j < 8; j++) {
                    uint4 bv = *(const uint4*)(pB + (tn * 8 + j) * 80 + cb);
#pragma unroll
                    for (int i = 0; i < 8; i++) {
                        int v = acc[i * 8 + j];
                        v = dp4a_us(av[i].x, bv.x, v);
                        v = dp4a_us(av[i].y, bv.y, v);
                        v = dp4a_us(av[i].z, bv.z, v);
                        v = dp4a_us(av[i].w, bv.w, v);
                        acc[i * 8 + j] = v;
                    }
                }
            }
        }
    }

    // ---------------- epilogue: stage via smem, coalesced NCHW stores --------
    __syncthreads();
    int* sep = (int*)smem;                // [128 oc][pitch 132]
    if (isIMMA) {
#pragma unroll
        for (int t = 0; t < 4; t++) {
            int m = warp_m * 64 + t * 16 + (lane >> 2);
#pragma unroll
            for (int u = 0; u < 4; u++) {
                int n = warp_n * 32 + u * 8 + 2 * (lane & 3);
                const int* a4 = &acc[(t * 4 + u) * 4];
                sep[n * 132 + m]           = a4[0];
                sep[(n + 1) * 132 + m]     = a4[1];
                sep[n * 132 + m + 8]       = a4[2];
                sep[(n + 1) * 132 + m + 8] = a4[3];
            }
        }
    } else {
#pragma unroll
        for (int j = 0; j < 8; j++)
#pragma unroll
            for (int i = 0; i < 8; i++)
                sep[(tn * 8 + j) * 132 + tm * 8 + i] = acc[i * 8 + j];
    }
    __syncthreads();

#pragma unroll 1
    for (int i = 0; i < 16; i++) {
        int ol = wid + i * 8;
        int oc = n0 + ol;
        float sc = d_scale[oc];
        float bv = __ldg(&bias[oc]);
        float* orow = out + ((size_t)(b * OC_ + oc)) * HW_ + q0;
#pragma unroll
        for (int qc = 0; qc < 4; qc++) {
            int m = qc * 32 + lane;
            if (q0 + m < HW_)
                orow[m] = fmaf(sc, (float)sep[ol * 132 + m], bv);
        }
    }
}

// ---------------- launch (conv is the 4th launch for ncu capture) ----------------
extern "C" void kernel_launch(void* const* d_in, const int* in_sizes, int n_in,
                              void* d_out, int out_size) {
    const float* x     = (const float*)d_in[0];
    const float* gamma = (const float*)d_in[1];
    const float* beta  = (const float*)d_in[2];
    const float* a     = (const float*)d_in[3];
    const float* wfp   = (const float*)d_in[4];
    const float* bias  = (const float*)d_in[5];
    float* out = (float*)d_out;
    (void)in_sizes; (void)n_in; (void)out_size;

    tern_kernel<<<OC_, 256>>>(wfp, a);
    gn_stats_kernel<<<B_ * 8, 512>>>(x);
    quant_kernel<<<dim3(110, 8, B_), dim3(32, 8)>>>(x, gamma, beta, a);

    cudaFuncSetAttribute(conv_mma_kernel,
                         cudaFuncAttributeMaxDynamicSharedMemorySize, SMEM_CONV);
    conv_mma_kernel<<<1600, 256, SMEM_CONV>>>(bias, out);
}

// round 10
// speedup vs baseline: 2.7876x; 1.0093x over previous
#include <cuda_runtime.h>
#include <cstdint>
#include <cstddef>

#define B_   32
#define C_   256
#define HW_  3136
#define OC_  256
#define PW   58                            // padded width/height
#define PQ   3492                          // 58*58 + 128 tail pad rows

// ---------------- scratch (device globals) ----------------
__device__ float d_mu[B_ * 8];
__device__ float d_rs[B_ * 8];
__device__ float d_scale[OC_];             // alpha_oc * a_c / 255
__device__ unsigned char d_hq[(size_t)B_ * PQ * 256];   // padded NHWC u8
__device__ signed char  d_ws[9 * 256 * 256];            // [tap][oc][ic] in {-1,0,1}

// ======================= PTX helpers =======================
__device__ __forceinline__ uint32_t smem_u32(const void* p) {
    uint32_t a;
    asm("{ .reg .u64 t; cvta.to.shared.u64 t, %1; cvt.u32.u64 %0, t; }" : "=r"(a) : "l"(p));
    return a;
}
#define CP16(dst, src) \
    asm volatile("cp.async.cg.shared.global [%0], [%1], 16;" :: "r"(dst), "l"(src) : "memory")
#define CP_COMMIT() asm volatile("cp.async.commit_group;" ::: "memory")
#define CP_WAIT3()  asm volatile("cp.async.wait_group 3;" ::: "memory")

__device__ __forceinline__ void ldsm4(uint32_t* r, uint32_t addr) {
    asm volatile("ldmatrix.sync.aligned.m8n8.x4.shared.b16 {%0,%1,%2,%3}, [%4];"
                 : "=r"(r[0]), "=r"(r[1]), "=r"(r[2]), "=r"(r[3]) : "r"(addr));
}
__device__ __forceinline__ void ldsm2(uint32_t* r, uint32_t addr) {
    asm volatile("ldmatrix.sync.aligned.m8n8.x2.shared.b16 {%0,%1}, [%2];"
                 : "=r"(r[0]), "=r"(r[1]) : "r"(addr));
}
__device__ __forceinline__ void mma_u8s8(int* c, const uint32_t* a, const uint32_t* b) {
    asm volatile(
        "mma.sync.aligned.m16n8k32.row.col.s32.u8.s8.s32 "
        "{%0,%1,%2,%3}, {%4,%5,%6,%7}, {%8,%9}, {%0,%1,%2,%3};"
        : "+r"(c[0]), "+r"(c[1]), "+r"(c[2]), "+r"(c[3])
        : "r"(a[0]), "r"(a[1]), "r"(a[2]), "r"(a[3]), "r"(b[0]), "r"(b[1]));
}
__device__ __forceinline__ int dp4a_us(unsigned a, unsigned b, int c) {
    int d;
    asm("dp4a.u32.s32 %0, %1, %2, %3;" : "=r"(d) : "r"(a), "r"(b), "r"(c));
    return d;
}

// ---------------- kernel 1: ternarize weights -> s8 [tap][oc][ic] ----------------
__global__ void tern_kernel(const float* __restrict__ w,
                            const float* __restrict__ a_ptr) {
    int oc = blockIdx.x, tid = threadIdx.x;
    const float* wp = w + (size_t)oc * 2304;
    __shared__ float red[256], red2[256];
    __shared__ float t_sh;

    float s = 0.f;
    for (int i = tid; i < 2304; i += 256) s += fabsf(wp[i]);
    red[tid] = s;
    __syncthreads();
    for (int o = 128; o; o >>= 1) {
        if (tid < o) red[tid] += red[tid + o];
        __syncthreads();
    }
    if (tid == 0) t_sh = 0.05f * red[0] / 2304.0f;
    __syncthreads();
    float t = t_sh;

    float sa = 0.f, sm = 0.f;
    for (int i = tid; i < 2304; i += 256) {
        float aw = fabsf(wp[i]);
        if (aw > t) { sa += aw; sm += 1.f; }
    }
    red[tid] = sa; red2[tid] = sm;
    __syncthreads();
    for (int o = 128; o; o >>= 1) {
        if (tid < o) { red[tid] += red[tid + o]; red2[tid] += red2[tid + o]; }
        __syncthreads();
    }
    if (tid == 0) {
        float alpha = red[0] / (red2[0] + 1e-8f);
        float a_c = fmaxf(a_ptr[0], 0.f) + 1e-8f;
        d_scale[oc] = alpha * a_c / 255.0f;
    }
    for (int i = tid; i < 2304; i += 256) {
        float wv = wp[i];
        signed char q = (fabsf(wv) > t) ? (wv > 0.f ? (signed char)1 : (signed char)-1)
                                        : (signed char)0;
        int ic = i / 9, k = i - ic * 9;    // tap = ky*3+kx
        d_ws[((size_t)k * 256 + oc) * 256 + ic] = q;
    }
}

// ---------------- kernel 2: GroupNorm statistics ----------------
__global__ void gn_stats_kernel(const float* __restrict__ x) {
    int bg = blockIdx.x;
    int b = bg >> 3, g = bg & 7;
    const float4* xp = (const float4*)(x + ((size_t)b * C_ + (size_t)g * 32) * HW_);
    const int N4 = 32 * HW_ / 4;
    int tid = threadIdx.x;
    float s = 0.f, s2 = 0.f;
#pragma unroll 4
    for (int i = tid; i < N4; i += 512) {
        float4 v = xp[i];
        s += v.x + v.y + v.z + v.w;
        s2 += v.x * v.x + v.y * v.y + v.z * v.z + v.w * v.w;
    }
    __shared__ float r1[512], r2[512];
    r1[tid] = s; r2[tid] = s2;
    __syncthreads();
    for (int o = 256; o; o >>= 1) {
        if (tid < o) { r1[tid] += r1[tid + o]; r2[tid] += r2[tid + o]; }
        __syncthreads();
    }
    if (tid == 0) {
        const float N = (float)(32 * HW_);
        float mu = r1[0] / N;
        float var = r2[0] / N - mu * mu;
        d_mu[bg] = mu;
        d_rs[bg] = rsqrtf(var + 1e-5f);
    }
}

// ---------------- kernel 3: GN + ReLU^2 + PACT quant + pad-zero (fused) ----------
// grid (110, 8, 32): x<98 quantize 32x32 tiles; x>=98 (y==0) zero pad rows.
__global__ void quant_kernel(const float* __restrict__ x,
                             const float* __restrict__ gamma,
                             const float* __restrict__ beta,
                             const float* __restrict__ a_ptr) {
    int b = blockIdx.z;
    int tx = threadIdx.x, ty = threadIdx.y;
    int tid = ty * 32 + tx;

    if (blockIdx.x >= 98) {                // pad-zero blocks
        if (blockIdx.y != 0) return;
        int slot = (blockIdx.x - 98) * 30 + (tid >> 3);
        if (slot >= 356) return;
        int r;
        if (slot < 58)        r = slot;                      // y=0
        else if (slot < 116)  r = 3306 + (slot - 58);        // y=57
        else if (slot < 172)  r = (slot - 115) * PW;         // x=0, y=1..56
        else if (slot < 228)  r = (slot - 171) * PW + 57;    // x=57, y=1..56
        else                  r = 3364 + (slot - 228);       // tail overread rows
        uint4* dst = (uint4*)(d_hq + ((size_t)b * PQ + r) * 256 + (tid & 7) * 32);
        dst[0] = make_uint4(0, 0, 0, 0);
        dst[1] = make_uint4(0, 0, 0, 0);
        return;
    }

    __shared__ unsigned char tile[32][33];
    int c0 = blockIdx.y * 32;
    int p0 = blockIdx.x * 32;

    float a_c = fmaxf(a_ptr[0], 0.f) + 1e-8f;
    float S = 255.f / a_c;
    float mu = d_mu[b * 8 + blockIdx.y];
    float rs = d_rs[b * 8 + blockIdx.y];

#pragma unroll
    for (int i = 0; i < 4; i++) {
        int cl = ty + i * 8;
        int c = c0 + cl;
        float v = x[((size_t)b * C_ + c) * HW_ + p0 + tx];
        float xn = (v - mu) * rs * gamma[c] + beta[c];
        float r = fmaxf(xn, 0.f);
        float h = r * r;
        float yv = fminf(h, a_c);
        tile[cl][tx] = (unsigned char)(int)rintf(yv * S);
    }
    __syncthreads();
#pragma unroll
    for (int i = 0; i < 4; i++) {
        int p = p0 + ty + i * 8;           // valid pixel 0..3135
        int y = p / 56, xx = p - y * 56;
        size_t r = (size_t)(y + 1) * PW + (xx + 1);
        d_hq[((size_t)b * PQ + r) * 256 + c0 + tx] = tile[tx][ty + i * 8];
    }
}

// ---------------- kernel 4: hybrid IMMA + dp4a implicit-GEMM conv ----------------
// 1600 CTAs flat. Role: (bid % 3) < 2 -> IMMA (1067 tiles, tensor pipe),
// else dp4a (533 tiles, fma pipe). Split = measured 2:1 per-tile cost ratio.
#define NST 5
#define STAGE_B 20480
#define SMEM_CONV (NST * STAGE_B)

__global__ void __launch_bounds__(256, 2)
conv_mma_kernel(const float* __restrict__ bias, float* __restrict__ out) {
    extern __shared__ char smem[];
    uint32_t sbase = smem_u32(smem);
    int tid = threadIdx.x;
    int wid = tid >> 5, lane = tid & 31;
    int bid = blockIdx.x;
    int b = bid / 50;
    int rem = bid - b * 50;
    int n0 = (rem / 25) * 128;
    int q0 = (rem % 25) * 128;
    bool isIMMA = (bid % 3) < 2;

    // cp.async loaders: threads 0..127 A row=tid, 128..255 B row=tid-128
    bool isA = tid < 128;
    int lrow = isA ? tid : tid - 128;
    int lsw = (lrow >> 3) & 3;             // store-side swizzle key
    uint32_t sdst0 = sbase + (isA ? 0u : 10240u) + (uint32_t)lrow * 80u;

    const char* gbase;
    if (isA) {
        int q = q0 + lrow;                 // tail tiles read zeroed pad rows
        int y = q / 56, xx = q - y * 56;
        gbase = (const char*)(d_hq + ((size_t)b * PQ + (size_t)(y * PW + xx)) * 256);
    } else {
        gbase = (const char*)(d_ws + (size_t)(n0 + lrow) * 256);
    }

    auto issue = [&](int s) {
        int st = s % NST;
        int tap = s >> 2, cc = s & 3;
        const char* g;
        if (isA) {
            int ky = tap / 3, kx = tap - ky * 3;
            g = gbase + (size_t)(ky * PW + kx) * 256 + cc * 64;
        } else {
            g = gbase + (size_t)tap * 65536 + cc * 64;
        }
        uint32_t d = sdst0 + (uint32_t)st * STAGE_B;
        CP16(d + ((0 ^ lsw) & 3) * 16, g);
        CP16(d + ((1 ^ lsw) & 3) * 16, g + 16);
        CP16(d + ((2 ^ lsw) & 3) * 16, g + 32);
        CP16(d + ((3 ^ lsw) & 3) * 16, g + 48);
        CP_COMMIT();
    };

    // shared accumulators (64 regs, disjoint role lifetimes)
    int acc[64];
#pragma unroll
    for (int i = 0; i < 64; i++) acc[i] = 0;

    // ---- IMMA per-lane read geometry ----
    int warp_m = wid >> 2, warp_n = wid & 3;
    int grp = lane >> 3, r8 = lane & 7;
    uint32_t a_base[4]; int a_swz[4]; int a_cb = grp >> 1;
#pragma unroll
    for (int t = 0; t < 4; t++) {
        int row = warp_m * 64 + t * 16 + (grp & 1) * 8 + r8;
        a_base[t] = sbase + (uint32_t)row * 80u;
        a_swz[t] = (row >> 3) & 3;
    }
    int bl = lane & 15;
    uint32_t b_base[4]; int b_swz[4]; int b_cb = bl >> 3;
#pragma unroll
    for (int u = 0; u < 4; u++) {
        int row = warp_n * 32 + u * 8 + (bl & 7);
        b_base[u] = sbase + 10240u + (uint32_t)row * 80u;
        b_swz[u] = (row >> 3) & 3;
    }

    // ---- dp4a thread geometry ----
    int tm = tid >> 4, tn = tid & 15;      // 8 pixels x 8 ocs per thread
    const char* sA = smem;                 // A rows at pitch 80
    const char* sB = smem + 10240;

    issue(0); issue(1); issue(2); issue(3);

#pragma unroll 1
    for (int s = 0; s < 36; s++) {
        int st = s % NST;
        CP_WAIT3();
        __syncthreads();
        if (s + 4 < 36) issue(s + 4);
        else CP_COMMIT();
        uint32_t so = (uint32_t)st * STAGE_B;

        if (isIMMA) {
#pragma unroll
            for (int ks = 0; ks < 2; ks++) {
                uint32_t afr[4][4], bfr[4][2];
#pragma unroll
                for (int t = 0; t < 4; t++) {
                    uint32_t c = (uint32_t)(((ks * 2 + a_cb) ^ a_swz[t]) & 3) * 16u;
                    ldsm4(afr[t], a_base[t] + so + c);
                }
#pragma unroll
                for (int u = 0; u < 4; u++) {
                    uint32_t c = (uint32_t)(((ks * 2 + b_cb) ^ b_swz[u]) & 3) * 16u;
                    ldsm2(bfr[u], b_base[u] + so + c);
                }
#pragma unroll
                for (int t = 0; t < 4; t++)
#pragma unroll
                    for (int u = 0; u < 4; u++)
                        mma_u8s8(&acc[(t * 4 + u) * 4], afr[t], bfr[u]);
            }
        } else {
            const char* pA = sA + so;
            const char* pB = sB + so;
#pragma unroll 1
            for (int kb = 0; kb < 4; kb++) {
                uint32_t ca = (uint32_t)((kb ^ tm) & 3) * 16u;   // m>>3 == tm
                uint32_t cb = (uint32_t)((kb ^ tn) & 3) * 16u;   // n>>3 == tn
                uint4 av[8];
#pragma unroll
                for (int i = 0; i < 8; i++)
                    av[i] = *(const uint4*)(pA + (tm * 8 + i) * 80 + ca);
#pragma unroll
                for (int j = 0; j < 8; j++) {
                    uint4 bv = *(const uint4*)(pB + (tn * 8 + j) * 80 + cb);
#pragma unroll
                    for (int i = 0; i < 8; i++) {
                        int v = acc[i * 8 + j];
                        v = dp4a_us(av[i].x, bv.x, v);
                        v = dp4a_us(av[i].y, bv.y, v);
                        v = dp4a_us(av[i].z, bv.z, v);
                        v = dp4a_us(av[i].w, bv.w, v);
                        acc[i * 8 + j] = v;
                    }
                }
            }
        }
    }

    // ---------------- epilogue: stage via smem, coalesced NCHW stores --------
    __syncthreads();
    int* sep = (int*)smem;                // [128 oc][pitch 132]
    if (isIMMA) {
#pragma unroll
        for (int t = 0; t < 4; t++) {
            int m = warp_m * 64 + t * 16 + (lane >> 2);
#pragma unroll
            for (int u = 0; u < 4; u++) {
                int n = warp_n * 32 + u * 8 + 2 * (lane & 3);
                const int* a4 = &acc[(t * 4 + u) * 4];
                sep[n * 132 + m]           = a4[0];
                sep[(n + 1) * 132 + m]     = a4[1];
                sep[n * 132 + m + 8]       = a4[2];
                sep[(n + 1) * 132 + m + 8] = a4[3];
            }
        }
    } else {
#pragma unroll
        for (int j = 0; j < 8; j++)
#pragma unroll
            for (int i = 0; i < 8; i++)
                sep[(tn * 8 + j) * 132 + tm * 8 + i] = acc[i * 8 + j];
    }
    __syncthreads();

#pragma unroll 1
    for (int i = 0; i < 16; i++) {
        int ol = wid + i * 8;
        int oc = n0 + ol;
        float sc = d_scale[oc];
        float bv = __ldg(&bias[oc]);
        float* orow = out + ((size_t)(b * OC_ + oc)) * HW_ + q0;
#pragma unroll
        for (int qc = 0; qc < 4; qc++) {
            int m = qc * 32 + lane;
            if (q0 + m < HW_)
                orow[m] = fmaf(sc, (float)sep[ol * 132 + m], bv);
        }
    }
}

// ---------------- launch (conv is the 4th launch for ncu capture) ----------------
extern "C" void kernel_launch(void* const* d_in, const int* in_sizes, int n_in,
                              void* d_out, int out_size) {
    const float* x     = (const float*)d_in[0];
    const float* gamma = (const float*)d_in[1];
    const float* beta  = (const float*)d_in[2];
    const float* a     = (const float*)d_in[3];
    const float* wfp   = (const float*)d_in[4];
    const float* bias  = (const float*)d_in[5];
    float* out = (float*)d_out;
    (void)in_sizes; (void)n_in; (void)out_size;

    tern_kernel<<<OC_, 256>>>(wfp, a);
    gn_stats_kernel<<<B_ * 8, 512>>>(x);
    quant_kernel<<<dim3(110, 8, B_), dim3(32, 8)>>>(x, gamma, beta, a);

    cudaFuncSetAttribute(conv_mma_kernel,
                         cudaFuncAttributeMaxDynamicSharedMemorySize, SMEM_CONV);
    conv_mma_kernel<<<1600, 256, SMEM_CONV>>>(bias, out);
}

// round 11
// speedup vs baseline: 2.8656x; 1.0280x over previous
#include <cuda_runtime.h>
#include <cstdint>
#include <cstddef>

#define B_   32
#define C_   256
#define HW_  3136
#define OC_  256
#define PW   58                            // padded width/height
#define PQ   3492                          // 58*58 + 128 tail pad rows

// ---------------- scratch (device globals) ----------------
__device__ float d_mu[B_ * 8];
__device__ float d_rs[B_ * 8];
__device__ float d_scale[OC_];             // alpha_oc * a_c / 255
__device__ unsigned char d_hq[(size_t)B_ * PQ * 256];   // padded NHWC u8
__device__ signed char  d_ws[9 * 256 * 256];            // [tap][oc][ic] in {-1,0,1}

// ======================= PTX helpers =======================
__device__ __forceinline__ uint32_t smem_u32(const void* p) {
    uint32_t a;
    asm("{ .reg .u64 t; cvta.to.shared.u64 t, %1; cvt.u32.u64 %0, t; }" : "=r"(a) : "l"(p));
    return a;
}
#define CP16(dst, src) \
    asm volatile("cp.async.cg.shared.global [%0], [%1], 16;" :: "r"(dst), "l"(src) : "memory")
#define CP_COMMIT() asm volatile("cp.async.commit_group;" ::: "memory")
#define CP_WAIT3()  asm volatile("cp.async.wait_group 3;" ::: "memory")

__device__ __forceinline__ void ldsm4(uint32_t* r, uint32_t addr) {
    asm volatile("ldmatrix.sync.aligned.m8n8.x4.shared.b16 {%0,%1,%2,%3}, [%4];"
                 : "=r"(r[0]), "=r"(r[1]), "=r"(r[2]), "=r"(r[3]) : "r"(addr));
}
__device__ __forceinline__ void ldsm2(uint32_t* r, uint32_t addr) {
    asm volatile("ldmatrix.sync.aligned.m8n8.x2.shared.b16 {%0,%1}, [%2];"
                 : "=r"(r[0]), "=r"(r[1]) : "r"(addr));
}
__device__ __forceinline__ void mma_u8s8(int* c, const uint32_t* a, const uint32_t* b) {
    asm volatile(
        "mma.sync.aligned.m16n8k32.row.col.s32.u8.s8.s32 "
        "{%0,%1,%2,%3}, {%4,%5,%6,%7}, {%8,%9}, {%0,%1,%2,%3};"
        : "+r"(c[0]), "+r"(c[1]), "+r"(c[2]), "+r"(c[3])
        : "r"(a[0]), "r"(a[1]), "r"(a[2]), "r"(a[3]), "r"(b[0]), "r"(b[1]));
}
__device__ __forceinline__ int dp4a_us(unsigned a, unsigned b, int c) {
    int d;
    asm("dp4a.u32.s32 %0, %1, %2, %3;" : "=r"(d) : "r"(a), "r"(b), "r"(c));
    return d;
}

// ---------------- kernel 1: ternarize weights -> s8 [tap][oc][ic] ----------------
__global__ void tern_kernel(const float* __restrict__ w,
                            const float* __restrict__ a_ptr) {
    int oc = blockIdx.x, tid = threadIdx.x;
    const float* wp = w + (size_t)oc * 2304;
    __shared__ float red[256], red2[256];
    __shared__ float t_sh;

    float s = 0.f;
    for (int i = tid; i < 2304; i += 256) s += fabsf(wp[i]);
    red[tid] = s;
    __syncthreads();
    for (int o = 128; o; o >>= 1) {
        if (tid < o) red[tid] += red[tid + o];
        __syncthreads();
    }
    if (tid == 0) t_sh = 0.05f * red[0] / 2304.0f;
    __syncthreads();
    float t = t_sh;

    float sa = 0.f, sm = 0.f;
    for (int i = tid; i < 2304; i += 256) {
        float aw = fabsf(wp[i]);
        if (aw > t) { sa += aw; sm += 1.f; }
    }
    red[tid] = sa; red2[tid] = sm;
    __syncthreads();
    for (int o = 128; o; o >>= 1) {
        if (tid < o) { red[tid] += red[tid + o]; red2[tid] += red2[tid + o]; }
        __syncthreads();
    }
    if (tid == 0) {
        float alpha = red[0] / (red2[0] + 1e-8f);
        float a_c = fmaxf(a_ptr[0], 0.f) + 1e-8f;
        d_scale[oc] = alpha * a_c / 255.0f;
    }
    for (int i = tid; i < 2304; i += 256) {
        float wv = wp[i];
        signed char q = (fabsf(wv) > t) ? (wv > 0.f ? (signed char)1 : (signed char)-1)
                                        : (signed char)0;
        int ic = i / 9, k = i - ic * 9;    // tap = ky*3+kx
        d_ws[((size_t)k * 256 + oc) * 256 + ic] = q;
    }
}

// ---------------- kernel 2: GroupNorm statistics ----------------
__global__ void gn_stats_kernel(const float* __restrict__ x) {
    int bg = blockIdx.x;
    int b = bg >> 3, g = bg & 7;
    const float4* xp = (const float4*)(x + ((size_t)b * C_ + (size_t)g * 32) * HW_);
    const int N4 = 32 * HW_ / 4;
    int tid = threadIdx.x;
    float s = 0.f, s2 = 0.f;
#pragma unroll 4
    for (int i = tid; i < N4; i += 512) {
        float4 v = xp[i];
        s += v.x + v.y + v.z + v.w;
        s2 += v.x * v.x + v.y * v.y + v.z * v.z + v.w * v.w;
    }
    __shared__ float r1[512], r2[512];
    r1[tid] = s; r2[tid] = s2;
    __syncthreads();
    for (int o = 256; o; o >>= 1) {
        if (tid < o) { r1[tid] += r1[tid + o]; r2[tid] += r2[tid + o]; }
        __syncthreads();
    }
    if (tid == 0) {
        const float N = (float)(32 * HW_);
        float mu = r1[0] / N;
        float var = r2[0] / N - mu * mu;
        d_mu[bg] = mu;
        d_rs[bg] = rsqrtf(var + 1e-5f);
    }
}

// ---------------- kernel 3: GN + ReLU^2 + PACT quant + pad-zero (fused) ----------
__global__ void quant_kernel(const float* __restrict__ x,
                             const float* __restrict__ gamma,
                             const float* __restrict__ beta,
                             const float* __restrict__ a_ptr) {
    int b = blockIdx.z;
    int tx = threadIdx.x, ty = threadIdx.y;
    int tid = ty * 32 + tx;

    if (blockIdx.x >= 98) {                // pad-zero blocks
        if (blockIdx.y != 0) return;
        int slot = (blockIdx.x - 98) * 30 + (tid >> 3);
        if (slot >= 356) return;
        int r;
        if (slot < 58)        r = slot;                      // y=0
        else if (slot < 116)  r = 3306 + (slot - 58);        // y=57
        else if (slot < 172)  r = (slot - 115) * PW;         // x=0, y=1..56
        else if (slot < 228)  r = (slot - 171) * PW + 57;    // x=57, y=1..56
        else                  r = 3364 + (slot - 228);       // tail overread rows
        uint4* dst = (uint4*)(d_hq + ((size_t)b * PQ + r) * 256 + (tid & 7) * 32);
        dst[0] = make_uint4(0, 0, 0, 0);
        dst[1] = make_uint4(0, 0, 0, 0);
        return;
    }

    __shared__ unsigned char tile[32][33];
    int c0 = blockIdx.y * 32;
    int p0 = blockIdx.x * 32;

    float a_c = fmaxf(a_ptr[0], 0.f) + 1e-8f;
    float S = 255.f / a_c;
    float mu = d_mu[b * 8 + blockIdx.y];
    float rs = d_rs[b * 8 + blockIdx.y];

#pragma unroll
    for (int i = 0; i < 4; i++) {
        int cl = ty + i * 8;
        int c = c0 + cl;
        float v = x[((size_t)b * C_ + c) * HW_ + p0 + tx];
        float xn = (v - mu) * rs * gamma[c] + beta[c];
        float r = fmaxf(xn, 0.f);
        float h = r * r;
        float yv = fminf(h, a_c);
        tile[cl][tx] = (unsigned char)(int)rintf(yv * S);
    }
    __syncthreads();
#pragma unroll
    for (int i = 0; i < 4; i++) {
        int p = p0 + ty + i * 8;           // valid pixel 0..3135
        int y = p / 56, xx = p - y * 56;
        size_t r = (size_t)(y + 1) * PW + (xx + 1);
        d_hq[((size_t)b * PQ + r) * 256 + c0 + tx] = tile[tx][ty + i * 8];
    }
}

// ---------------- kernel 4: hybrid IMMA + dp4a conv, 128x64 tiles -------------
// 3200 CTAs: bid -> b = bid/100, n0 = ((bid%100)/25)*64, q0 = ((bid%100)%25)*128.
// Role: (bid % 15) < 8 -> IMMA (tensor), else dp4a (fma). 3 CTAs/SM, 24 warps/SM.
// smem/stage: A 128x80 (10240) + B 64x80 (5120) = 15360; 5 stages = 76800 B.
#define NST 5
#define STAGE_B 15360
#define SMEM_CONV (NST * STAGE_B)

__global__ void __launch_bounds__(256, 3)
conv_mma_kernel(const float* __restrict__ bias, float* __restrict__ out) {
    extern __shared__ char smem[];
    uint32_t sbase = smem_u32(smem);
    int tid = threadIdx.x;
    int wid = tid >> 5, lane = tid & 31;
    int bid = blockIdx.x;
    int b = bid / 100;
    int rem = bid - b * 100;
    int n0 = (rem / 25) * 64;
    int q0 = (rem % 25) * 128;
    bool isIMMA = (bid % 15) < 8;

    // loaders: tid<128 -> A row tid; tid in [128,192) -> B row tid-128; else none
    bool isA = tid < 128;
    bool isLd = tid < 192;
    int lrow = isA ? tid : tid - 128;
    int lsw = (lrow >> 3) & 3;
    uint32_t sdst0 = sbase + (isA ? 0u : 10240u) + (uint32_t)lrow * 80u;

    const char* gbase;
    if (isA) {
        int q = q0 + lrow;                 // tail tiles read zeroed pad rows
        int y = q / 56, xx = q - y * 56;
        gbase = (const char*)(d_hq + ((size_t)b * PQ + (size_t)(y * PW + xx)) * 256);
    } else {
        gbase = (const char*)(d_ws + (size_t)(n0 + lrow) * 256);
    }

    auto issue = [&](int s) {
        int st = s % NST;
        if (isLd) {
            int tap = s >> 2, cc = s & 3;
            const char* g;
            if (isA) {
                int ky = tap / 3, kx = tap - ky * 3;
                g = gbase + (size_t)(ky * PW + kx) * 256 + cc * 64;
            } else {
                g = gbase + (size_t)tap * 65536 + cc * 64;
            }
            uint32_t d = sdst0 + (uint32_t)st * STAGE_B;
            CP16(d + ((0 ^ lsw) & 3) * 16, g);
            CP16(d + ((1 ^ lsw) & 3) * 16, g + 16);
            CP16(d + ((2 ^ lsw) & 3) * 16, g + 32);
            CP16(d + ((3 ^ lsw) & 3) * 16, g + 48);
        }
        CP_COMMIT();
    };

    // 32 accumulator regs (disjoint role lifetimes)
    int acc[32];
#pragma unroll
    for (int i = 0; i < 32; i++) acc[i] = 0;

    // ---- IMMA geometry: warp tile 64x16; warp_m = wid>>2 (2), warp_n = wid&3 (4) ----
    int warp_m = wid >> 2, warp_n = wid & 3;
    int grp = lane >> 3, r8 = lane & 7;
    uint32_t a_base[4]; int a_swz[4]; int a_cb = grp >> 1;
#pragma unroll
    for (int t = 0; t < 4; t++) {
        int row = warp_m * 64 + t * 16 + (grp & 1) * 8 + r8;
        a_base[t] = sbase + (uint32_t)row * 80u;
        a_swz[t] = (row >> 3) & 3;
    }
    int bl = lane & 15;
    uint32_t b_base[2]; int b_swz[2]; int b_cb = bl >> 3;
#pragma unroll
    for (int u = 0; u < 2; u++) {
        int row = warp_n * 16 + u * 8 + (bl & 7);
        b_base[u] = sbase + 10240u + (uint32_t)row * 80u;
        b_swz[u] = (row >> 3) & 3;
    }

    // ---- dp4a geometry: 8 pixels x 4 ocs per thread ----
    int tm = tid >> 4, tn = tid & 15;      // pix rows tm*8+i, oc rows tn*4+j
    int tns = tn >> 1;                     // (tn*4+j)>>3 for j<4
    const char* sA = smem;
    const char* sB = smem + 10240;

    issue(0); issue(1); issue(2); issue(3);

#pragma unroll 1
    for (int s = 0; s < 36; s++) {
        int st = s % NST;
        CP_WAIT3();
        __syncthreads();
        if (s + 4 < 36) issue(s + 4);
        else CP_COMMIT();
        uint32_t so = (uint32_t)st * STAGE_B;

        if (isIMMA) {
#pragma unroll
            for (int ks = 0; ks < 2; ks++) {
                uint32_t afr[4][4], bfr[2][2];
#pragma unroll
                for (int t = 0; t < 4; t++) {
                    uint32_t c = (uint32_t)(((ks * 2 + a_cb) ^ a_swz[t]) & 3) * 16u;
                    ldsm4(afr[t], a_base[t] + so + c);
                }
#pragma unroll
                for (int u = 0; u < 2; u++) {
                    uint32_t c = (uint32_t)(((ks * 2 + b_cb) ^ b_swz[u]) & 3) * 16u;
                    ldsm2(bfr[u], b_base[u] + so + c);
                }
#pragma unroll
                for (int t = 0; t < 4; t++)
#pragma unroll
                    for (int u = 0; u < 2; u++)
                        mma_u8s8(&acc[(t * 2 + u) * 4], afr[t], bfr[u]);
            }
        } else {
            const char* pA = sA + so;
            const char* pB = sB + so;
#pragma unroll 1
            for (int kb = 0; kb < 4; kb++) {
                uint32_t ca = (uint32_t)((kb ^ tm) & 3) * 16u;    // av rows>>3 == tm
                uint32_t cb = (uint32_t)((kb ^ tns) & 3) * 16u;   // bv rows>>3 == tn>>1
                uint4 av[8];
#pragma unroll
                for (int i = 0; i < 8; i++)
                    av[i] = *(const uint4*)(pA + (tm * 8 + i) * 80 + ca);
#pragma unroll
                for (int j = 0; j < 4; j++) {
                    uint4 bv = *(const uint4*)(pB + (tn * 4 + j) * 80 + cb);
#pragma unroll
                    for (int i = 0; i < 8; i++) {
                        int v = acc[i * 4 + j];
                        v = dp4a_us(av[i].x, bv.x, v);
                        v = dp4a_us(av[i].y, bv.y, v);
                        v = dp4a_us(av[i].z, bv.z, v);
                        v = dp4a_us(av[i].w, bv.w, v);
                        acc[i * 4 + j] = v;
                    }
                }
            }
        }
    }

    // ---------------- epilogue: stage via smem, coalesced NCHW stores --------
    __syncthreads();
    int* sep = (int*)smem;                // [64 oc][pitch 132]
    if (isIMMA) {
#pragma unroll
        for (int t = 0; t < 4; t++) {
            int m = warp_m * 64 + t * 16 + (lane >> 2);
#pragma unroll
            for (int u = 0; u < 2; u++) {
                int n = warp_n * 16 + u * 8 + 2 * (lane & 3);
                const int* a4 = &acc[(t * 2 + u) * 4];
                sep[n * 132 + m]           = a4[0];
                sep[(n + 1) * 132 + m]     = a4[1];
                sep[n * 132 + m + 8]       = a4[2];
                sep[(n + 1) * 132 + m + 8] = a4[3];
            }
        }
    } else {
#pragma unroll
        for (int j = 0; j < 4; j++)
#pragma unroll
            for (int i = 0; i < 8; i++)
                sep[(tn * 4 + j) * 132 + tm * 8 + i] = acc[i * 4 + j];
    }
    __syncthreads();

#pragma unroll 1
    for (int i = 0; i < 8; i++) {
        int ol = wid + i * 8;
        int oc = n0 + ol;
        float sc = d_scale[oc];
        float bv = __ldg(&bias[oc]);
        float* orow = out + ((size_t)(b * OC_ + oc)) * HW_ + q0;
#pragma unroll
        for (int qc = 0; qc < 4; qc++) {
            int m = qc * 32 + lane;
            if (q0 + m < HW_)
                orow[m] = fmaf(sc, (float)sep[ol * 132 + m], bv);
        }
    }
}

// ---------------- launch (conv is the 4th launch for ncu capture) ----------------
extern "C" void kernel_launch(void* const* d_in, const int* in_sizes, int n_in,
                              void* d_out, int out_size) {
    const float* x     = (const float*)d_in[0];
    const float* gamma = (const float*)d_in[1];
    const float* beta  = (const float*)d_in[2];
    const float* a     = (const float*)d_in[3];
    const float* wfp   = (const float*)d_in[4];
    const float* bias  = (const float*)d_in[5];
    float* out = (float*)d_out;
    (void)in_sizes; (void)n_in; (void)out_size;

    tern_kernel<<<OC_, 256>>>(wfp, a);
    gn_stats_kernel<<<B_ * 8, 512>>>(x);
    quant_kernel<<<dim3(110, 8, B_), dim3(32, 8)>>>(x, gamma, beta, a);

    cudaFuncSetAttribute(conv_mma_kernel,
                         cudaFuncAttributeMaxDynamicSharedMemorySize, SMEM_CONV);
    conv_mma_kernel<<<3200, 256, SMEM_CONV>>>(bias, out);
}